// round 10
// baseline (speedup 1.0000x reference)
#include <cuda_runtime.h>
#include <cstdint>

#define N_ROWS 16384
#define FEATS  512
#define HID    256
#define CLS    64
#define NITER  10

// ---------------- scratch ----------------
__device__ float g_W[FEATS * CLS];
__device__ float g_bias[CLS];
__device__ float g_Z0[N_ROWS * CLS];
__device__ float g_Zfinal[N_ROWS * CLS];
__device__ uint32_t g_ZT[2][CLS * N_ROWS];   // Z^T [class][node], tf32 bits

__device__ __forceinline__ uint32_t f2tf32(float f) {
    uint32_t u;
    asm volatile("cvt.rna.tf32.f32 %0, %1;\n" : "=r"(u) : "f"(f));
    return u;
}
__device__ __forceinline__ uint32_t cvt_reg_tf32(uint32_t v) {
    uint32_t u;
    asm volatile("cvt.rna.tf32.f32 %0, %1;\n" : "=r"(u) : "f"(__uint_as_float(v)));
    return u;
}
__device__ __forceinline__ uint32_t smem_u32_of(const void* p) {
    uint32_t a;
    asm("{ .reg .u64 t; cvta.to.shared.u64 t, %1; cvt.u32.u64 %0, t; }" : "=r"(a) : "l"(p));
    return a;
}
__device__ __forceinline__ void ldmatrix_x4(uint32_t& r0, uint32_t& r1,
                                            uint32_t& r2, uint32_t& r3, uint32_t a) {
    asm volatile("ldmatrix.sync.aligned.m8n8.x4.shared.b16 {%0,%1,%2,%3}, [%4];\n"
                 : "=r"(r0), "=r"(r1), "=r"(r2), "=r"(r3) : "r"(a));
}
__device__ __forceinline__ void mma_tf32(float c[4],
                                         uint32_t a0, uint32_t a1, uint32_t a2, uint32_t a3,
                                         uint32_t b0, uint32_t b1) {
    asm volatile(
        "mma.sync.aligned.m16n8k8.row.col.f32.tf32.tf32.f32 "
        "{%0,%1,%2,%3}, {%4,%5,%6,%7}, {%8,%9}, {%0,%1,%2,%3};\n"
        : "+f"(c[0]), "+f"(c[1]), "+f"(c[2]), "+f"(c[3])
        : "r"(a0), "r"(a1), "r"(a2), "r"(a3), "r"(b0), "r"(b1));
}
__device__ __forceinline__ void mbar_init(uint32_t a, uint32_t cnt) {
    asm volatile("mbarrier.init.shared.b64 [%0], %1;" :: "r"(a), "r"(cnt) : "memory");
}
__device__ __forceinline__ void mbar_expect_tx(uint32_t a, uint32_t bytes) {
    asm volatile("mbarrier.arrive.expect_tx.shared.b64 _, [%0], %1;"
                 :: "r"(a), "r"(bytes) : "memory");
}
__device__ __forceinline__ void mbar_wait(uint32_t a, uint32_t parity) {
    uint32_t done;
    asm volatile("{\n\t.reg .pred p;\n\t"
        "mbarrier.try_wait.parity.acquire.cta.shared::cta.b64 p, [%1], %2;\n\t"
        "selp.b32 %0, 1, 0, p;\n\t}" : "=r"(done) : "r"(a), "r"(parity) : "memory");
    if (!done) {
        asm volatile("{\n\t.reg .pred P1;\n\t"
            "W%=:\n\t"
            "mbarrier.try_wait.parity.acquire.cta.shared::cta.b64 P1, [%0], %1, 0x989680;\n\t"
            "@P1 bra.uni D%=;\n\t"
            "bra.uni W%=;\n\t"
            "D%=:\n\t}" :: "r"(a), "r"(parity) : "memory");
    }
}
__device__ __forceinline__ void bulk_cp(uint32_t dst_smem, const void* src, uint32_t bytes,
                                        uint32_t mbar) {
    asm volatile(
        "cp.async.bulk.shared::cta.global.mbarrier::complete_tx::bytes [%0], [%1], %2, [%3];"
        :: "r"(dst_smem), "l"(src), "r"(bytes), "r"(mbar) : "memory");
}

// ---------------- kernel 1: collapse the MLP ----------------
__global__ void fuse_w_kernel(const float* __restrict__ W1, const float* __restrict__ b1,
                              const float* __restrict__ W2, const float* __restrict__ b2) {
    int idx = blockIdx.x * blockDim.x + threadIdx.x;
    if (idx < FEATS * CLS) {
        int f = idx / CLS, c = idx % CLS;
        float s = 0.f;
        #pragma unroll 8
        for (int k = 0; k < HID; k++) s += W1[f * HID + k] * W2[k * CLS + c];
        g_W[idx] = s;
    } else if (idx < FEATS * CLS + CLS) {
        int c = idx - FEATS * CLS;
        float s = b2[c];
        for (int k = 0; k < HID; k++) s += b1[k] * W2[k * CLS + c];
        g_bias[c] = s;
    }
}

// ---------------- kernel 2: Z0 = h @ W + bias ----------------
#define Z0_BM 64
#define Z0_BK 16
__global__ __launch_bounds__(256)
void z0_kernel(const float* __restrict__ h) {
    __shared__ float As[Z0_BM][Z0_BK + 1];
    __shared__ float Bs[Z0_BK][CLS + 1];
    int bm = blockIdx.x * Z0_BM;
    int tx = threadIdx.x % 16, ty = threadIdx.x / 16;
    float acc[4][4];
    #pragma unroll
    for (int i = 0; i < 4; i++)
        #pragma unroll
        for (int j = 0; j < 4; j++) acc[i][j] = 0.f;

    for (int k0 = 0; k0 < FEATS; k0 += Z0_BK) {
        for (int i = threadIdx.x; i < Z0_BM * Z0_BK; i += 256) {
            int r = i / Z0_BK, c = i % Z0_BK;
            As[r][c] = h[(size_t)(bm + r) * FEATS + k0 + c];
        }
        for (int i = threadIdx.x; i < Z0_BK * CLS; i += 256) {
            int r = i / CLS, c = i % CLS;
            Bs[r][c] = g_W[(k0 + r) * CLS + c];
        }
        __syncthreads();
        #pragma unroll
        for (int kk = 0; kk < Z0_BK; kk++) {
            float a[4], b[4];
            #pragma unroll
            for (int i = 0; i < 4; i++) a[i] = As[ty * 4 + i][kk];
            #pragma unroll
            for (int j = 0; j < 4; j++) b[j] = Bs[kk][tx * 4 + j];
            #pragma unroll
            for (int i = 0; i < 4; i++)
                #pragma unroll
                for (int j = 0; j < 4; j++) acc[i][j] += a[i] * b[j];
        }
        __syncthreads();
    }
    #pragma unroll
    for (int i = 0; i < 4; i++)
        #pragma unroll
        for (int j = 0; j < 4; j++) {
            int r = bm + ty * 4 + i, c = tx * 4 + j;
            float y = acc[i][j] + g_bias[c];
            g_Z0[(size_t)r * CLS + c] = y;
            g_ZT[0][c * N_ROWS + r] = f2tf32(y);
        }
}

// ---------------- kernel 3: propagation (mma.sync tf32, bulk-copy pipeline) ----------------
#define BM 128
#define SBK 64                 // k per stage
#define NST (N_ROWS / SBK)     // 256 stages
#define STAGES 3
#define ROW_W 68               // words/row: 64 data + 4 pad; 4r mod 32 distinct over octet
#define ROW_BYTES (SBK * 4)    // 256 bytes copied per row
#define ASZ (BM * ROW_W)       // words
#define BSZ (CLS * ROW_W)
#define STAGE_W (ASZ + BSZ)
#define STAGE_BYTES_TX ((BM + CLS) * ROW_BYTES)      // 49152 tx bytes per stage
#define MBAR_AREA 64
#define SMEM_BYTES (MBAR_AREA + STAGES * STAGE_W * 4)  // 64 + 156672

__global__ __launch_bounds__(256, 1)
void prop_kernel(const float* __restrict__ adj, int it) {
    const int rb = it & 1, wb = rb ^ 1;
    const uint32_t* ZTin = g_ZT[rb];

    extern __shared__ uint32_t sm[];
    const uint32_t smem0 = smem_u32_of(sm);
    const uint32_t data0 = smem0 + MBAR_AREA;

    const int tid   = threadIdx.x;
    const int lane  = tid & 31;
    const int warp  = tid >> 5;
    const int warpM = warp >> 1;        // 0..3, 32 rows
    const int warpN = warp & 1;         // 0..1, 32 cols
    const int bm    = blockIdx.x * BM;
    const int lr    = lane & 7;
    const int lg    = lane >> 3;

    if (tid < STAGES) mbar_init(smem0 + tid * 8, 1);
    __syncthreads();

    // per-thread bulk-copy assignment: tid<128 -> A row tid; 128<=tid<192 -> B row tid-128
    auto issue_stage = [&](int st) {
        const int s = st % STAGES;
        const int k0 = st * SBK;
        const uint32_t mbar = smem0 + s * 8;
        if (tid < BM) {
            bulk_cp(data0 + (s * STAGE_W + tid * ROW_W) * 4,
                    adj + (size_t)(bm + tid) * N_ROWS + k0, ROW_BYTES, mbar);
        } else if (tid < BM + CLS) {
            int n = tid - BM;
            bulk_cp(data0 + (s * STAGE_W + ASZ + n * ROW_W) * 4,
                    ZTin + (size_t)n * N_ROWS + k0, ROW_BYTES, mbar);
        }
    };

    // prologue: stages 0 and 1
    if (tid == 0) { mbar_expect_tx(smem0 + 0, STAGE_BYTES_TX);
                    mbar_expect_tx(smem0 + 8, STAGE_BYTES_TX); }
    __syncthreads();
    issue_stage(0);
    issue_stage(1);

    float acc[2][4][4];
    #pragma unroll
    for (int mt = 0; mt < 2; mt++)
        #pragma unroll
        for (int nt = 0; nt < 4; nt++)
            #pragma unroll
            for (int i = 0; i < 4; i++) acc[mt][nt][i] = 0.f;

    const uint32_t a_row0 = warpM * 32 + lr + (lg & 1) * 8;
    const uint32_t a_koff = (lg >> 1) * 4;
    const uint32_t b_row0 = warpN * 32 + lr + (lg >> 1) * 8;
    const uint32_t b_koff = (lg & 1) * 4;

    for (int st = 0; st < NST; st++) {
        mbar_wait(smem0 + (st % STAGES) * 8, (st / STAGES) & 1);
        if (tid == 0 && st + 2 < NST)
            mbar_expect_tx(smem0 + ((st + 2) % STAGES) * 8, STAGE_BYTES_TX);
        __syncthreads();     // all warps done with stage st-1's slot; expect_tx visible
        if (st + 2 < NST) issue_stage(st + 2);

        const uint32_t base = data0 + ((st % STAGES) * STAGE_W) * 4;

        #pragma unroll
        for (int half = 0; half < 2; half++) {
            float ctile[2][4][4];
            #pragma unroll
            for (int mt = 0; mt < 2; mt++)
                #pragma unroll
                for (int nt = 0; nt < 4; nt++)
                    #pragma unroll
                    for (int i = 0; i < 4; i++) ctile[mt][nt][i] = 0.f;

            #pragma unroll
            for (int kk = 0; kk < 4; kk++) {
                const uint32_t koff = half * 32 + kk * 8;
                uint32_t a[2][4];
                #pragma unroll
                for (int mt = 0; mt < 2; mt++) {
                    ldmatrix_x4(a[mt][0], a[mt][1], a[mt][2], a[mt][3],
                                base + ((a_row0 + mt * 16) * ROW_W + koff + a_koff) * 4);
                    #pragma unroll
                    for (int q = 0; q < 4; q++) a[mt][q] = cvt_reg_tf32(a[mt][q]);
                }
                #pragma unroll
                for (int ntp = 0; ntp < 2; ntp++) {
                    uint32_t b0, b1, b2, b3;
                    ldmatrix_x4(b0, b1, b2, b3,
                                base + (ASZ + (b_row0 + ntp * 16) * ROW_W + koff + b_koff) * 4);
                    #pragma unroll
                    for (int mt = 0; mt < 2; mt++) {
                        mma_tf32(ctile[mt][ntp * 2],     a[mt][0], a[mt][1], a[mt][2], a[mt][3], b0, b1);
                        mma_tf32(ctile[mt][ntp * 2 + 1], a[mt][0], a[mt][1], a[mt][2], a[mt][3], b2, b3);
                    }
                }
            }
            #pragma unroll
            for (int mt = 0; mt < 2; mt++)
                #pragma unroll
                for (int nt = 0; nt < 4; nt++)
                    #pragma unroll
                    for (int i = 0; i < 4; i++) acc[mt][nt][i] += ctile[mt][nt][i];
        }
    }

    // epilogue: y = 0.9*acc + 0.1*Z0 ; ZT tf32 always; fp32 at last iter
    #pragma unroll
    for (int mt = 0; mt < 2; mt++) {
        #pragma unroll
        for (int nt = 0; nt < 4; nt++) {
            int r0 = bm + warpM * 32 + mt * 16 + (lane >> 2);
            int c0 = warpN * 32 + (nt >> 1) * 16 + (nt & 1) * 8 + (lane & 3) * 2;
            #pragma unroll
            for (int i = 0; i < 4; i++) {
                int r = r0 + ((i >= 2) ? 8 : 0);
                int c = c0 + (i & 1);
                size_t idx = (size_t)r * CLS + c;
                float y = 0.9f * acc[mt][nt][i] + 0.1f * g_Z0[idx];
                g_ZT[wb][c * N_ROWS + r] = f2tf32(y);
                if (it == NITER - 1) g_Zfinal[idx] = y;
            }
        }
    }

    __syncthreads();
    if (tid < STAGES)
        asm volatile("mbarrier.inval.shared.b64 [%0];" :: "r"(smem0 + tid * 8) : "memory");
}

// ---------------- kernel 4: log_softmax ----------------
__global__ __launch_bounds__(256)
void lsm_kernel(float* __restrict__ out) {
    int row  = blockIdx.x * 8 + (threadIdx.x >> 5);
    int lane = threadIdx.x & 31;
    const float* zr = g_Zfinal + (size_t)row * CLS;
    float v0 = zr[lane], v1 = zr[lane + 32];
    float m = fmaxf(v0, v1);
    #pragma unroll
    for (int o = 16; o > 0; o >>= 1) m = fmaxf(m, __shfl_xor_sync(0xffffffffu, m, o));
    float e = expf(v0 - m) + expf(v1 - m);
    #pragma unroll
    for (int o = 16; o > 0; o >>= 1) e += __shfl_xor_sync(0xffffffffu, e, o);
    float l = m + logf(e);
    out[(size_t)row * CLS + lane]      = v0 - l;
    out[(size_t)row * CLS + lane + 32] = v1 - l;
}

// ---------------- launch ----------------
extern "C" void kernel_launch(void* const* d_in, const int* in_sizes, int n_in,
                              void* d_out, int out_size) {
    const float *h = nullptr, *adj = nullptr, *W1 = nullptr,
                *b1 = nullptr, *W2 = nullptr, *b2 = nullptr;
    for (int i = 0; i < n_in; i++) {
        switch (in_sizes[i]) {
            case N_ROWS * FEATS:  h   = (const float*)d_in[i]; break;
            case 268435456:       adj = (const float*)d_in[i]; break;
            case FEATS * HID:     W1  = (const float*)d_in[i]; break;
            case HID:             b1  = (const float*)d_in[i]; break;
            case HID * CLS:       W2  = (const float*)d_in[i]; break;
            case CLS:             b2  = (const float*)d_in[i]; break;
            default: break;
        }
    }

    cudaFuncSetAttribute(prop_kernel, cudaFuncAttributeMaxDynamicSharedMemorySize,
                         SMEM_BYTES);

    fuse_w_kernel<<<(FEATS * CLS + CLS + 255) / 256, 256>>>(W1, b1, W2, b2);
    z0_kernel<<<N_ROWS / Z0_BM, 256>>>(h);
    for (int it = 0; it < NITER; it++)
        prop_kernel<<<N_ROWS / BM, 256, SMEM_BYTES>>>(adj, it);
    lsm_kernel<<<N_ROWS / 8, 256>>>((float*)d_out);
}

// round 11
// speedup vs baseline: 1.1764x; 1.1764x over previous
#include <cuda_runtime.h>
#include <cstdint>

#define N_ROWS 16384
#define FEATS  512
#define HID    256
#define CLS    64
#define NITER  10

// ---------------- scratch ----------------
__device__ float g_W[FEATS * CLS];
__device__ float g_bias[CLS];
__device__ float g_Z0[N_ROWS * CLS];
__device__ float g_Zfinal[N_ROWS * CLS];
__device__ uint32_t g_ZT[2][CLS * N_ROWS];   // Z^T [class][node], tf32 bits

__device__ __forceinline__ uint32_t f2tf32(float f) {
    uint32_t u;
    asm volatile("cvt.rna.tf32.f32 %0, %1;\n" : "=r"(u) : "f"(f));
    return u;
}
__device__ __forceinline__ uint32_t cvt_reg_tf32(uint32_t v) {
    uint32_t u;
    asm volatile("cvt.rna.tf32.f32 %0, %1;\n" : "=r"(u) : "f"(__uint_as_float(v)));
    return u;
}
__device__ __forceinline__ uint32_t smem_u32_of(const void* p) {
    uint32_t a;
    asm("{ .reg .u64 t; cvta.to.shared.u64 t, %1; cvt.u32.u64 %0, t; }" : "=r"(a) : "l"(p));
    return a;
}
__device__ __forceinline__ void cp_async16(uint32_t smem, const void* gmem) {
    asm volatile("cp.async.cg.shared.global [%0], [%1], 16;\n" :: "r"(smem), "l"(gmem));
}
__device__ __forceinline__ void ldmatrix_x4(uint32_t& r0, uint32_t& r1,
                                            uint32_t& r2, uint32_t& r3, uint32_t a) {
    asm volatile("ldmatrix.sync.aligned.m8n8.x4.shared.b16 {%0,%1,%2,%3}, [%4];\n"
                 : "=r"(r0), "=r"(r1), "=r"(r2), "=r"(r3) : "r"(a));
}
__device__ __forceinline__ void mma_tf32(float c[4],
                                         uint32_t a0, uint32_t a1, uint32_t a2, uint32_t a3,
                                         uint32_t b0, uint32_t b1) {
    asm volatile(
        "mma.sync.aligned.m16n8k8.row.col.f32.tf32.tf32.f32 "
        "{%0,%1,%2,%3}, {%4,%5,%6,%7}, {%8,%9}, {%0,%1,%2,%3};\n"
        : "+f"(c[0]), "+f"(c[1]), "+f"(c[2]), "+f"(c[3])
        : "r"(a0), "r"(a1), "r"(a2), "r"(a3), "r"(b0), "r"(b1));
}

// ---------------- kernel 1: collapse the MLP ----------------
__global__ void fuse_w_kernel(const float* __restrict__ W1, const float* __restrict__ b1,
                              const float* __restrict__ W2, const float* __restrict__ b2) {
    int idx = blockIdx.x * blockDim.x + threadIdx.x;
    if (idx < FEATS * CLS) {
        int f = idx / CLS, c = idx % CLS;
        float s = 0.f;
        #pragma unroll 8
        for (int k = 0; k < HID; k++) s += W1[f * HID + k] * W2[k * CLS + c];
        g_W[idx] = s;
    } else if (idx < FEATS * CLS + CLS) {
        int c = idx - FEATS * CLS;
        float s = b2[c];
        for (int k = 0; k < HID; k++) s += b1[k] * W2[k * CLS + c];
        g_bias[c] = s;
    }
}

// ---------------- kernel 2: Z0 = h @ W + bias ----------------
#define Z0_BM 64
#define Z0_BK 16
__global__ __launch_bounds__(256)
void z0_kernel(const float* __restrict__ h) {
    __shared__ float As[Z0_BM][Z0_BK + 1];
    __shared__ float Bs[Z0_BK][CLS + 1];
    int bm = blockIdx.x * Z0_BM;
    int tx = threadIdx.x % 16, ty = threadIdx.x / 16;
    float acc[4][4];
    #pragma unroll
    for (int i = 0; i < 4; i++)
        #pragma unroll
        for (int j = 0; j < 4; j++) acc[i][j] = 0.f;

    for (int k0 = 0; k0 < FEATS; k0 += Z0_BK) {
        for (int i = threadIdx.x; i < Z0_BM * Z0_BK; i += 256) {
            int r = i / Z0_BK, c = i % Z0_BK;
            As[r][c] = h[(size_t)(bm + r) * FEATS + k0 + c];
        }
        for (int i = threadIdx.x; i < Z0_BK * CLS; i += 256) {
            int r = i / CLS, c = i % CLS;
            Bs[r][c] = g_W[(k0 + r) * CLS + c];
        }
        __syncthreads();
        #pragma unroll
        for (int kk = 0; kk < Z0_BK; kk++) {
            float a[4], b[4];
            #pragma unroll
            for (int i = 0; i < 4; i++) a[i] = As[ty * 4 + i][kk];
            #pragma unroll
            for (int j = 0; j < 4; j++) b[j] = Bs[kk][tx * 4 + j];
            #pragma unroll
            for (int i = 0; i < 4; i++)
                #pragma unroll
                for (int j = 0; j < 4; j++) acc[i][j] += a[i] * b[j];
        }
        __syncthreads();
    }
    #pragma unroll
    for (int i = 0; i < 4; i++)
        #pragma unroll
        for (int j = 0; j < 4; j++) {
            int r = bm + ty * 4 + i, c = tx * 4 + j;
            float y = acc[i][j] + g_bias[c];
            g_Z0[(size_t)r * CLS + c] = y;
            g_ZT[0][c * N_ROWS + r] = f2tf32(y);
        }
}

// ---------------- kernel 3: propagation (tf32 mma, BM=64, 2 CTAs/SM) ----------------
#define BM 64
#define SBK 64                 // k per stage
#define NST (N_ROWS / SBK)     // 256 stages
#define STAGES 3
#define ROW_W 68               // words/row: 64 data + 4 pad
#define ASZ (BM * ROW_W)       // 4352 words
#define BSZ (CLS * ROW_W)      // 4352 words
#define STAGE_W (ASZ + BSZ)    // 8704 words
#define SMEM_BYTES (STAGES * STAGE_W * 4)   // 104448

__global__ __launch_bounds__(256, 2)
void prop_kernel(const float* __restrict__ adj, int it) {
    const int rb = it & 1, wb = rb ^ 1;
    const uint32_t* ZTin = g_ZT[rb];

    extern __shared__ uint32_t sm[];
    const uint32_t smem0 = smem_u32_of(sm);

    const int tid   = threadIdx.x;
    const int lane  = tid & 31;
    const int warp  = tid >> 5;
    const int warpM = warp >> 1;        // 0..3, 16 rows each
    const int warpN = warp & 1;         // 0..1, 32 cols each
    const int bm    = blockIdx.x * BM;
    const int lr    = lane & 7;
    const int lg    = lane >> 3;

    auto load_stage = [&](int s, int st) {
        const int k0 = st * SBK;
        const uint32_t base = smem0 + (s * STAGE_W) * 4;
        #pragma unroll
        for (int j = 0; j < 4; j++) {          // A: 64 rows x 16 float4
            int ch = tid + j * 256;
            int r = ch >> 4, c4 = (ch & 15) * 4;
            cp_async16(base + (r * ROW_W + c4) * 4,
                       adj + (size_t)(bm + r) * N_ROWS + k0 + c4);
        }
        #pragma unroll
        for (int j = 0; j < 4; j++) {          // B: 64 class-rows x 16 float4
            int ch = tid + j * 256;
            int n = ch >> 4, c4 = (ch & 15) * 4;
            cp_async16(base + (ASZ + n * ROW_W + c4) * 4,
                       ZTin + (size_t)n * N_ROWS + k0 + c4);
        }
        asm volatile("cp.async.commit_group;\n");
    };

    float acc[4][4];
    #pragma unroll
    for (int nt = 0; nt < 4; nt++)
        #pragma unroll
        for (int i = 0; i < 4; i++) acc[nt][i] = 0.f;

    load_stage(0, 0);
    load_stage(1, 1);

    const uint32_t a_row0 = warpM * 16 + lr + (lg & 1) * 8;
    const uint32_t a_koff = (lg >> 1) * 4;
    const uint32_t b_row0 = warpN * 32 + lr + (lg >> 1) * 8;
    const uint32_t b_koff = (lg & 1) * 4;

    for (int st = 0; st < NST; st++) {
        asm volatile("cp.async.wait_group 1;\n");
        __syncthreads();

        int ns = st + 2;
        if (ns < NST) load_stage(ns % STAGES, ns);
        else          asm volatile("cp.async.commit_group;\n");

        const uint32_t base = smem0 + ((st % STAGES) * STAGE_W) * 4;

        #pragma unroll
        for (int half = 0; half < 2; half++) {
            float ctile[4][4];
            #pragma unroll
            for (int nt = 0; nt < 4; nt++)
                #pragma unroll
                for (int i = 0; i < 4; i++) ctile[nt][i] = 0.f;

            #pragma unroll
            for (int kk = 0; kk < 4; kk++) {
                const uint32_t koff = half * 32 + kk * 8;
                uint32_t a0, a1, a2, a3;
                ldmatrix_x4(a0, a1, a2, a3,
                            base + (a_row0 * ROW_W + koff + a_koff) * 4);
                a0 = cvt_reg_tf32(a0); a1 = cvt_reg_tf32(a1);
                a2 = cvt_reg_tf32(a2); a3 = cvt_reg_tf32(a3);
                #pragma unroll
                for (int ntp = 0; ntp < 2; ntp++) {
                    uint32_t b0, b1, b2, b3;
                    ldmatrix_x4(b0, b1, b2, b3,
                                base + (ASZ + (b_row0 + ntp * 16) * ROW_W + koff + b_koff) * 4);
                    mma_tf32(ctile[ntp * 2],     a0, a1, a2, a3, b0, b1);
                    mma_tf32(ctile[ntp * 2 + 1], a0, a1, a2, a3, b2, b3);
                }
            }
            #pragma unroll
            for (int nt = 0; nt < 4; nt++)
                #pragma unroll
                for (int i = 0; i < 4; i++) acc[nt][i] += ctile[nt][i];
        }
    }

    // epilogue: y = 0.9*acc + 0.1*Z0 ; ZT tf32 always; fp32 at last iter
    #pragma unroll
    for (int nt = 0; nt < 4; nt++) {
        int r0 = bm + warpM * 16 + (lane >> 2);
        int c0 = warpN * 32 + (nt >> 1) * 16 + (nt & 1) * 8 + (lane & 3) * 2;
        #pragma unroll
        for (int i = 0; i < 4; i++) {
            int r = r0 + ((i >= 2) ? 8 : 0);
            int c = c0 + (i & 1);
            size_t idx = (size_t)r * CLS + c;
            float y = 0.9f * acc[nt][i] + 0.1f * g_Z0[idx];
            g_ZT[wb][c * N_ROWS + r] = f2tf32(y);
            if (it == NITER - 1) g_Zfinal[idx] = y;
        }
    }
}

// ---------------- kernel 4: log_softmax ----------------
__global__ __launch_bounds__(256)
void lsm_kernel(float* __restrict__ out) {
    int row  = blockIdx.x * 8 + (threadIdx.x >> 5);
    int lane = threadIdx.x & 31;
    const float* zr = g_Zfinal + (size_t)row * CLS;
    float v0 = zr[lane], v1 = zr[lane + 32];
    float m = fmaxf(v0, v1);
    #pragma unroll
    for (int o = 16; o > 0; o >>= 1) m = fmaxf(m, __shfl_xor_sync(0xffffffffu, m, o));
    float e = expf(v0 - m) + expf(v1 - m);
    #pragma unroll
    for (int o = 16; o > 0; o >>= 1) e += __shfl_xor_sync(0xffffffffu, e, o);
    float l = m + logf(e);
    out[(size_t)row * CLS + lane]      = v0 - l;
    out[(size_t)row * CLS + lane + 32] = v1 - l;
}

// ---------------- launch ----------------
extern "C" void kernel_launch(void* const* d_in, const int* in_sizes, int n_in,
                              void* d_out, int out_size) {
    const float *h = nullptr, *adj = nullptr, *W1 = nullptr,
                *b1 = nullptr, *W2 = nullptr, *b2 = nullptr;
    for (int i = 0; i < n_in; i++) {
        switch (in_sizes[i]) {
            case N_ROWS * FEATS:  h   = (const float*)d_in[i]; break;
            case 268435456:       adj = (const float*)d_in[i]; break;
            case FEATS * HID:     W1  = (const float*)d_in[i]; break;
            case HID:             b1  = (const float*)d_in[i]; break;
            case HID * CLS:       W2  = (const float*)d_in[i]; break;
            case CLS:             b2  = (const float*)d_in[i]; break;
            default: break;
        }
    }

    cudaFuncSetAttribute(prop_kernel, cudaFuncAttributeMaxDynamicSharedMemorySize,
                         SMEM_BYTES);

    fuse_w_kernel<<<(FEATS * CLS + CLS + 255) / 256, 256>>>(W1, b1, W2, b2);
    z0_kernel<<<N_ROWS / Z0_BM, 256>>>(h);
    for (int it = 0; it < NITER; it++)
        prop_kernel<<<N_ROWS / BM, 256, SMEM_BYTES>>>(adj, it);
    lsm_kernel<<<N_ROWS / 8, 256>>>((float*)d_out);
}

// round 12
// speedup vs baseline: 1.4059x; 1.1951x over previous
#include <cuda_runtime.h>
#include <cstdint>

#define N_ROWS 16384
#define FEATS  512
#define HID    256
#define CLS    64
#define NITER  10

// ---------------- scratch ----------------
__device__ float g_W[FEATS * CLS];
__device__ float g_bias[CLS];
__device__ float g_Z0[N_ROWS * CLS];
__device__ float g_Zfinal[N_ROWS * CLS];
__device__ uint32_t g_ZT[2][CLS * N_ROWS];   // Z^T [class][node], tf32 bits
// adj repacked: [tile(128 rows)][stage(64 k)] -> 128x64 tf32 words, granule-swizzled
__device__ uint32_t g_adjT[(size_t)N_ROWS * N_ROWS];

__device__ __forceinline__ uint32_t f2tf32(float f) {
    uint32_t u;
    asm volatile("cvt.rna.tf32.f32 %0, %1;\n" : "=r"(u) : "f"(f));
    return u;
}
__device__ __forceinline__ uint32_t smem_u32_of(const void* p) {
    uint32_t a;
    asm("{ .reg .u64 t; cvta.to.shared.u64 t, %1; cvt.u32.u64 %0, t; }" : "=r"(a) : "l"(p));
    return a;
}
__device__ __forceinline__ void cp_async16(uint32_t smem, const void* gmem) {
    asm volatile("cp.async.cg.shared.global [%0], [%1], 16;\n" :: "r"(smem), "l"(gmem));
}
__device__ __forceinline__ void ldmatrix_x4(uint32_t& r0, uint32_t& r1,
                                            uint32_t& r2, uint32_t& r3, uint32_t a) {
    asm volatile("ldmatrix.sync.aligned.m8n8.x4.shared.b16 {%0,%1,%2,%3}, [%4];\n"
                 : "=r"(r0), "=r"(r1), "=r"(r2), "=r"(r3) : "r"(a));
}
__device__ __forceinline__ void mma_tf32(float c[4],
                                         uint32_t a0, uint32_t a1, uint32_t a2, uint32_t a3,
                                         uint32_t b0, uint32_t b1) {
    asm volatile(
        "mma.sync.aligned.m16n8k8.row.col.f32.tf32.tf32.f32 "
        "{%0,%1,%2,%3}, {%4,%5,%6,%7}, {%8,%9}, {%0,%1,%2,%3};\n"
        : "+f"(c[0]), "+f"(c[1]), "+f"(c[2]), "+f"(c[3])
        : "r"(a0), "r"(a1), "r"(a2), "r"(a3), "r"(b0), "r"(b1));
}

// ---------------- kernel 1: collapse the MLP ----------------
__global__ void fuse_w_kernel(const float* __restrict__ W1, const float* __restrict__ b1,
                              const float* __restrict__ W2, const float* __restrict__ b2) {
    int idx = blockIdx.x * blockDim.x + threadIdx.x;
    if (idx < FEATS * CLS) {
        int f = idx / CLS, c = idx % CLS;
        float s = 0.f;
        #pragma unroll 8
        for (int k = 0; k < HID; k++) s += W1[f * HID + k] * W2[k * CLS + c];
        g_W[idx] = s;
    } else if (idx < FEATS * CLS + CLS) {
        int c = idx - FEATS * CLS;
        float s = b2[c];
        for (int k = 0; k < HID; k++) s += b1[k] * W2[k * CLS + c];
        g_bias[c] = s;
    }
}

// ---------------- kernel 2: Z0 = h @ W + bias ----------------
#define Z0_BM 64
#define Z0_BK 16
__global__ __launch_bounds__(256)
void z0_kernel(const float* __restrict__ h) {
    __shared__ float As[Z0_BM][Z0_BK + 1];
    __shared__ float Bs[Z0_BK][CLS + 1];
    int bm = blockIdx.x * Z0_BM;
    int tx = threadIdx.x % 16, ty = threadIdx.x / 16;
    float acc[4][4];
    #pragma unroll
    for (int i = 0; i < 4; i++)
        #pragma unroll
        for (int j = 0; j < 4; j++) acc[i][j] = 0.f;

    for (int k0 = 0; k0 < FEATS; k0 += Z0_BK) {
        for (int i = threadIdx.x; i < Z0_BM * Z0_BK; i += 256) {
            int r = i / Z0_BK, c = i % Z0_BK;
            As[r][c] = h[(size_t)(bm + r) * FEATS + k0 + c];
        }
        for (int i = threadIdx.x; i < Z0_BK * CLS; i += 256) {
            int r = i / CLS, c = i % CLS;
            Bs[r][c] = g_W[(k0 + r) * CLS + c];
        }
        __syncthreads();
        #pragma unroll
        for (int kk = 0; kk < Z0_BK; kk++) {
            float a[4], b[4];
            #pragma unroll
            for (int i = 0; i < 4; i++) a[i] = As[ty * 4 + i][kk];
            #pragma unroll
            for (int j = 0; j < 4; j++) b[j] = Bs[kk][tx * 4 + j];
            #pragma unroll
            for (int i = 0; i < 4; i++)
                #pragma unroll
                for (int j = 0; j < 4; j++) acc[i][j] += a[i] * b[j];
        }
        __syncthreads();
    }
    #pragma unroll
    for (int i = 0; i < 4; i++)
        #pragma unroll
        for (int j = 0; j < 4; j++) {
            int r = bm + ty * 4 + i, c = tx * 4 + j;
            float y = acc[i][j] + g_bias[c];
            g_Z0[(size_t)r * CLS + c] = y;
            g_ZT[0][c * N_ROWS + r] = f2tf32(y);
        }
}

// ---------------- kernel 3: repack adj -> tiled tf32 images ----------------
// block b handles adj rows [8b, 8b+8). Reads coalesced row-major; writes
// per-(tile,stage) images: word = tile_base + rl*64 + (gi ^ (rl&7))*4 + w.
__global__ __launch_bounds__(256)
void repack_kernel(const float* __restrict__ adj) {
    const int b = blockIdx.x;
    const int tid = threadIdx.x;
    #pragma unroll 4
    for (int j = 0; j < 128; j++) {
        int fl = tid + j * 256;              // 0..32767 float4-granules in this block
        int r_loc = fl >> 12;                // row within the 8-row band
        int kg = fl & 4095;                  // float4-granule within row (k = 4*kg)
        int r = b * 8 + r_loc;
        const float4 v = *(const float4*)(adj + (size_t)r * N_ROWS + kg * 4);
        uint4 o;
        o.x = f2tf32(v.x); o.y = f2tf32(v.y); o.z = f2tf32(v.z); o.w = f2tf32(v.w);
        int t  = r >> 7;                     // 128-row tile
        int rl = r & 127;
        int s  = kg >> 4;                    // 64-k stage
        int gi = kg & 15;                    // granule within row
        int gsw = gi ^ (rl & 7);             // baked swizzle
        size_t off = ((size_t)t * 256 + s) * 8192 + rl * 64 + gsw * 4;
        *(uint4*)(g_adjT + off) = o;
    }
}

// ---------------- kernel 4: propagation (tf32 mma, contiguous A tiles) ----------------
#define BM 128
#define SBK 64                 // k per stage
#define NST (N_ROWS / SBK)     // 256 stages
#define STAGES 3
#define A_W (BM * SBK)         // 8192 words/stage, no padding (swizzled)
#define B_ROW_W 68             // B: 64 data + 4 pad words per class-row
#define B_W (CLS * B_ROW_W)    // 4352 words
#define STAGE_W (A_W + B_W)    // 12544 words
#define SMEM_BYTES (STAGES * STAGE_W * 4)   // 150528

__global__ __launch_bounds__(256, 1)
void prop_kernel(int it) {
    const int rb = it & 1, wb = rb ^ 1;
    const uint32_t* ZTin = g_ZT[rb];

    extern __shared__ uint32_t sm[];
    const uint32_t smem0 = smem_u32_of(sm);

    const int tid   = threadIdx.x;
    const int lane  = tid & 31;
    const int warp  = tid >> 5;
    const int warpM = warp >> 1;        // 0..3, 32 rows
    const int warpN = warp & 1;         // 0..1, 32 cols
    const int tile  = blockIdx.x;       // 128-row tile index
    const int bm    = tile * BM;
    const int lr    = lane & 7;
    const int lg    = lane >> 3;

    auto load_stage = [&](int s, int st) {
        const uint32_t base = smem0 + (s * STAGE_W) * 4;
        const uint32_t* asrc = g_adjT + ((size_t)tile * 256 + st) * 8192;
        #pragma unroll
        for (int j = 0; j < 8; j++) {          // A: 2048 contiguous 16B chunks
            int ch = tid + j * 256;
            cp_async16(base + ch * 16, asrc + ch * 4);
        }
        const int k0 = st * SBK;
        #pragma unroll
        for (int j = 0; j < 4; j++) {          // B: 64 class-rows x 16 float4
            int ch = tid + j * 256;
            int n = ch >> 4, c4 = (ch & 15) * 4;
            cp_async16(base + (A_W + n * B_ROW_W + c4) * 4,
                       ZTin + (size_t)n * N_ROWS + k0 + c4);
        }
        asm volatile("cp.async.commit_group;\n");
    };

    float acc[2][4][4];
    #pragma unroll
    for (int mt = 0; mt < 2; mt++)
        #pragma unroll
        for (int nt = 0; nt < 4; nt++)
            #pragma unroll
            for (int i = 0; i < 4; i++) acc[mt][nt][i] = 0.f;

    load_stage(0, 0);
    load_stage(1, 1);

    const uint32_t a_row0 = warpM * 32 + lr + (lg & 1) * 8;   // + mt*16
    const uint32_t a_g    = lg >> 1;                          // + half*8 + kk*2
    const uint32_t b_row0 = warpN * 32 + lr + (lg >> 1) * 8;  // + ntp*16
    const uint32_t b_koff = (lg & 1) * 4;

    for (int st = 0; st < NST; st++) {
        asm volatile("cp.async.wait_group 1;\n");
        __syncthreads();

        int ns = st + 2;
        if (ns < NST) load_stage(ns % STAGES, ns);
        else          asm volatile("cp.async.commit_group;\n");

        const uint32_t base = smem0 + ((st % STAGES) * STAGE_W) * 4;

        #pragma unroll
        for (int half = 0; half < 2; half++) {
            float ctile[2][4][4];
            #pragma unroll
            for (int mt = 0; mt < 2; mt++)
                #pragma unroll
                for (int nt = 0; nt < 4; nt++)
                    #pragma unroll
                    for (int i = 0; i < 4; i++) ctile[mt][nt][i] = 0.f;

            #pragma unroll
            for (int kk = 0; kk < 4; kk++) {
                uint32_t a[2][4];
                #pragma unroll
                for (int mt = 0; mt < 2; mt++) {
                    uint32_t row = a_row0 + mt * 16;
                    uint32_t gi  = half * 8 + kk * 2 + a_g;
                    uint32_t w   = row * 64 + ((gi ^ (row & 7)) << 2);
                    ldmatrix_x4(a[mt][0], a[mt][1], a[mt][2], a[mt][3], base + w * 4);
                }
                const uint32_t koff = half * 32 + kk * 8;
                #pragma unroll
                for (int ntp = 0; ntp < 2; ntp++) {
                    uint32_t b0, b1, b2, b3;
                    ldmatrix_x4(b0, b1, b2, b3,
                                base + (A_W + (b_row0 + ntp * 16) * B_ROW_W + koff + b_koff) * 4);
                    #pragma unroll
                    for (int mt = 0; mt < 2; mt++) {
                        mma_tf32(ctile[mt][ntp * 2],     a[mt][0], a[mt][1], a[mt][2], a[mt][3], b0, b1);
                        mma_tf32(ctile[mt][ntp * 2 + 1], a[mt][0], a[mt][1], a[mt][2], a[mt][3], b2, b3);
                    }
                }
            }
            #pragma unroll
            for (int mt = 0; mt < 2; mt++)
                #pragma unroll
                for (int nt = 0; nt < 4; nt++)
                    #pragma unroll
                    for (int i = 0; i < 4; i++) acc[mt][nt][i] += ctile[mt][nt][i];
        }
    }

    // epilogue: y = 0.9*acc + 0.1*Z0 ; ZT tf32 always; fp32 at last iter
    #pragma unroll
    for (int mt = 0; mt < 2; mt++) {
        #pragma unroll
        for (int nt = 0; nt < 4; nt++) {
            int r0 = bm + warpM * 32 + mt * 16 + (lane >> 2);
            int c0 = warpN * 32 + (nt >> 1) * 16 + (nt & 1) * 8 + (lane & 3) * 2;
            #pragma unroll
            for (int i = 0; i < 4; i++) {
                int r = r0 + ((i >= 2) ? 8 : 0);
                int c = c0 + (i & 1);
                size_t idx = (size_t)r * CLS + c;
                float y = 0.9f * acc[mt][nt][i] + 0.1f * g_Z0[idx];
                g_ZT[wb][c * N_ROWS + r] = f2tf32(y);
                if (it == NITER - 1) g_Zfinal[idx] = y;
            }
        }
    }
}

// ---------------- kernel 5: log_softmax ----------------
__global__ __launch_bounds__(256)
void lsm_kernel(float* __restrict__ out) {
    int row  = blockIdx.x * 8 + (threadIdx.x >> 5);
    int lane = threadIdx.x & 31;
    const float* zr = g_Zfinal + (size_t)row * CLS;
    float v0 = zr[lane], v1 = zr[lane + 32];
    float m = fmaxf(v0, v1);
    #pragma unroll
    for (int o = 16; o > 0; o >>= 1) m = fmaxf(m, __shfl_xor_sync(0xffffffffu, m, o));
    float e = expf(v0 - m) + expf(v1 - m);
    #pragma unroll
    for (int o = 16; o > 0; o >>= 1) e += __shfl_xor_sync(0xffffffffu, e, o);
    float l = m + logf(e);
    out[(size_t)row * CLS + lane]      = v0 - l;
    out[(size_t)row * CLS + lane + 32] = v1 - l;
}

// ---------------- launch ----------------
extern "C" void kernel_launch(void* const* d_in, const int* in_sizes, int n_in,
                              void* d_out, int out_size) {
    const float *h = nullptr, *adj = nullptr, *W1 = nullptr,
                *b1 = nullptr, *W2 = nullptr, *b2 = nullptr;
    for (int i = 0; i < n_in; i++) {
        switch (in_sizes[i]) {
            case N_ROWS * FEATS:  h   = (const float*)d_in[i]; break;
            case 268435456:       adj = (const float*)d_in[i]; break;
            case FEATS * HID:     W1  = (const float*)d_in[i]; break;
            case HID:             b1  = (const float*)d_in[i]; break;
            case HID * CLS:       W2  = (const float*)d_in[i]; break;
            case CLS:             b2  = (const float*)d_in[i]; break;
            default: break;
        }
    }

    cudaFuncSetAttribute(prop_kernel, cudaFuncAttributeMaxDynamicSharedMemorySize,
                         SMEM_BYTES);

    fuse_w_kernel<<<(FEATS * CLS + CLS + 255) / 256, 256>>>(W1, b1, W2, b2);
    z0_kernel<<<N_ROWS / Z0_BM, 256>>>(h);
    repack_kernel<<<N_ROWS / 8, 256>>>(adj);
    for (int it = 0; it < NITER; it++)
        prop_kernel<<<N_ROWS / BM, 256, SMEM_BYTES>>>(it);
    lsm_kernel<<<N_ROWS / 8, 256>>>((float*)d_out);
}

// round 13
// speedup vs baseline: 1.4233x; 1.0124x over previous
#include <cuda_runtime.h>
#include <cstdint>

#define N_ROWS 16384
#define FEATS  512
#define HID    256
#define CLS    64
#define NITER  10

// ---------------- scratch ----------------
__device__ float g_W[FEATS * CLS];
__device__ float g_bias[CLS];
__device__ float g_Z0[N_ROWS * CLS];
__device__ float g_Zfinal[N_ROWS * CLS];
__device__ uint32_t g_ZT[2][CLS * N_ROWS];   // Z^T [class][node], tf32 bits
// adj repacked: [tile(128 rows)][stage(64 k)] -> 128x64 tf32 words, granule-swizzled
__device__ uint32_t g_adjT[(size_t)N_ROWS * N_ROWS];

__device__ __forceinline__ uint32_t f2tf32(float f) {
    uint32_t u;
    asm volatile("cvt.rna.tf32.f32 %0, %1;\n" : "=r"(u) : "f"(f));
    return u;
}
__device__ __forceinline__ uint32_t smem_u32_of(const void* p) {
    uint32_t a;
    asm("{ .reg .u64 t; cvta.to.shared.u64 t, %1; cvt.u32.u64 %0, t; }" : "=r"(a) : "l"(p));
    return a;
}
__device__ __forceinline__ void cp_async16(uint32_t smem, const void* gmem) {
    asm volatile("cp.async.cg.shared.global [%0], [%1], 16;\n" :: "r"(smem), "l"(gmem));
}
__device__ __forceinline__ void ldmatrix_x4(uint32_t& r0, uint32_t& r1,
                                            uint32_t& r2, uint32_t& r3, uint32_t a) {
    asm volatile("ldmatrix.sync.aligned.m8n8.x4.shared.b16 {%0,%1,%2,%3}, [%4];\n"
                 : "=r"(r0), "=r"(r1), "=r"(r2), "=r"(r3) : "r"(a));
}
__device__ __forceinline__ void mma_tf32(float c[4],
                                         uint32_t a0, uint32_t a1, uint32_t a2, uint32_t a3,
                                         uint32_t b0, uint32_t b1) {
    asm volatile(
        "mma.sync.aligned.m16n8k8.row.col.f32.tf32.tf32.f32 "
        "{%0,%1,%2,%3}, {%4,%5,%6,%7}, {%8,%9}, {%0,%1,%2,%3};\n"
        : "+f"(c[0]), "+f"(c[1]), "+f"(c[2]), "+f"(c[3])
        : "r"(a0), "r"(a1), "r"(a2), "r"(a3), "r"(b0), "r"(b1));
}

// ---------------- kernel 1: collapse the MLP ----------------
__global__ void fuse_w_kernel(const float* __restrict__ W1, const float* __restrict__ b1,
                              const float* __restrict__ W2, const float* __restrict__ b2) {
    int idx = blockIdx.x * blockDim.x + threadIdx.x;
    if (idx < FEATS * CLS) {
        int f = idx / CLS, c = idx % CLS;
        float s = 0.f;
        #pragma unroll 8
        for (int k = 0; k < HID; k++) s += W1[f * HID + k] * W2[k * CLS + c];
        g_W[idx] = s;
    } else if (idx < FEATS * CLS + CLS) {
        int c = idx - FEATS * CLS;
        float s = b2[c];
        for (int k = 0; k < HID; k++) s += b1[k] * W2[k * CLS + c];
        g_bias[c] = s;
    }
}

// ---------------- kernel 2: Z0 = h @ W + bias ----------------
#define Z0_BM 64
#define Z0_BK 16
__global__ __launch_bounds__(256)
void z0_kernel(const float* __restrict__ h) {
    __shared__ float As[Z0_BM][Z0_BK + 1];
    __shared__ float Bs[Z0_BK][CLS + 1];
    int bm = blockIdx.x * Z0_BM;
    int tx = threadIdx.x % 16, ty = threadIdx.x / 16;
    float acc[4][4];
    #pragma unroll
    for (int i = 0; i < 4; i++)
        #pragma unroll
        for (int j = 0; j < 4; j++) acc[i][j] = 0.f;

    for (int k0 = 0; k0 < FEATS; k0 += Z0_BK) {
        for (int i = threadIdx.x; i < Z0_BM * Z0_BK; i += 256) {
            int r = i / Z0_BK, c = i % Z0_BK;
            As[r][c] = h[(size_t)(bm + r) * FEATS + k0 + c];
        }
        for (int i = threadIdx.x; i < Z0_BK * CLS; i += 256) {
            int r = i / CLS, c = i % CLS;
            Bs[r][c] = g_W[(k0 + r) * CLS + c];
        }
        __syncthreads();
        #pragma unroll
        for (int kk = 0; kk < Z0_BK; kk++) {
            float a[4], b[4];
            #pragma unroll
            for (int i = 0; i < 4; i++) a[i] = As[ty * 4 + i][kk];
            #pragma unroll
            for (int j = 0; j < 4; j++) b[j] = Bs[kk][tx * 4 + j];
            #pragma unroll
            for (int i = 0; i < 4; i++)
                #pragma unroll
                for (int j = 0; j < 4; j++) acc[i][j] += a[i] * b[j];
        }
        __syncthreads();
    }
    #pragma unroll
    for (int i = 0; i < 4; i++)
        #pragma unroll
        for (int j = 0; j < 4; j++) {
            int r = bm + ty * 4 + i, c = tx * 4 + j;
            float y = acc[i][j] + g_bias[c];
            g_Z0[(size_t)r * CLS + c] = y;
            g_ZT[0][c * N_ROWS + r] = f2tf32(y);
        }
}

// ---------------- kernel 3: repack adj -> tiled tf32 images ----------------
__global__ __launch_bounds__(256)
void repack_kernel(const float* __restrict__ adj) {
    const int b = blockIdx.x;
    const int tid = threadIdx.x;
    #pragma unroll 4
    for (int j = 0; j < 128; j++) {
        int fl = tid + j * 256;              // 0..32767 float4-granules in this block
        int r_loc = fl >> 12;                // row within the 8-row band
        int kg = fl & 4095;                  // float4-granule within row
        int r = b * 8 + r_loc;
        const float4 v = *(const float4*)(adj + (size_t)r * N_ROWS + kg * 4);
        uint4 o;
        o.x = f2tf32(v.x); o.y = f2tf32(v.y); o.z = f2tf32(v.z); o.w = f2tf32(v.w);
        int t  = r >> 7;
        int rl = r & 127;
        int s  = kg >> 4;
        int gi = kg & 15;
        int gsw = gi ^ (rl & 7);             // baked swizzle
        size_t off = ((size_t)t * 256 + s) * 8192 + rl * 64 + gsw * 4;
        *(uint4*)(g_adjT + off) = o;
    }
}

// ---------------- kernel 4: propagation (tf32 mma, 4-stage deep pipeline) ----------------
#define BM 128
#define SBK 64                 // k per stage
#define NST (N_ROWS / SBK)     // 256 stages
#define STAGES 4
#define A_W (BM * SBK)         // 8192 words/stage (swizzled image)
#define B_ROW_W 68
#define B_W (CLS * B_ROW_W)    // 4352 words
#define STAGE_W (A_W + B_W)    // 12544 words
#define SMEM_BYTES (STAGES * STAGE_W * 4)   // 200704

__global__ __launch_bounds__(256, 1)
void prop_kernel(int it) {
    const int rb = it & 1, wb = rb ^ 1;
    const uint32_t* ZTin = g_ZT[rb];

    extern __shared__ uint32_t sm[];
    const uint32_t smem0 = smem_u32_of(sm);

    const int tid   = threadIdx.x;
    const int lane  = tid & 31;
    const int warp  = tid >> 5;
    const int warpM = warp >> 1;        // 0..3, 32 rows
    const int warpN = warp & 1;         // 0..1, 32 cols
    const int tile  = blockIdx.x;
    const int bm    = tile * BM;
    const int lr    = lane & 7;
    const int lg    = lane >> 3;

    auto load_stage = [&](int s, int st) {
        const uint32_t base = smem0 + (s * STAGE_W) * 4;
        const uint32_t* asrc = g_adjT + ((size_t)tile * 256 + st) * 8192;
        #pragma unroll
        for (int j = 0; j < 8; j++) {          // A: 2048 contiguous 16B chunks
            int ch = tid + j * 256;
            cp_async16(base + ch * 16, asrc + ch * 4);
        }
        const int k0 = st * SBK;
        #pragma unroll
        for (int j = 0; j < 4; j++) {          // B: 64 class-rows x 16 float4
            int ch = tid + j * 256;
            int n = ch >> 4, c4 = (ch & 15) * 4;
            cp_async16(base + (A_W + n * B_ROW_W + c4) * 4,
                       ZTin + (size_t)n * N_ROWS + k0 + c4);
        }
        asm volatile("cp.async.commit_group;\n");
    };

    float acc[2][4][4];
    #pragma unroll
    for (int mt = 0; mt < 2; mt++)
        #pragma unroll
        for (int nt = 0; nt < 4; nt++)
            #pragma unroll
            for (int i = 0; i < 4; i++) acc[mt][nt][i] = 0.f;

    load_stage(0, 0);
    load_stage(1, 1);
    load_stage(2, 2);

    const uint32_t a_row0 = warpM * 32 + lr + (lg & 1) * 8;   // + mt*16
    const uint32_t a_g    = lg >> 1;                          // + half*8 + kk*2
    const uint32_t b_row0 = warpN * 32 + lr + (lg >> 1) * 8;  // + ntp*16
    const uint32_t b_koff = (lg & 1) * 4;

    for (int st = 0; st < NST; st++) {
        asm volatile("cp.async.wait_group 2;\n");
        __syncthreads();

        int ns = st + 3;
        if (ns < NST) load_stage(ns & (STAGES - 1), ns);
        else          asm volatile("cp.async.commit_group;\n");

        const uint32_t base = smem0 + ((st & (STAGES - 1)) * STAGE_W) * 4;

        #pragma unroll
        for (int half = 0; half < 2; half++) {
            float ctile[2][4][4];
            #pragma unroll
            for (int mt = 0; mt < 2; mt++)
                #pragma unroll
                for (int nt = 0; nt < 4; nt++)
                    #pragma unroll
                    for (int i = 0; i < 4; i++) ctile[mt][nt][i] = 0.f;

            #pragma unroll
            for (int kk = 0; kk < 4; kk++) {
                uint32_t a[2][4];
                #pragma unroll
                for (int mt = 0; mt < 2; mt++) {
                    uint32_t row = a_row0 + mt * 16;
                    uint32_t gi  = half * 8 + kk * 2 + a_g;
                    uint32_t w   = row * 64 + ((gi ^ (row & 7)) << 2);
                    ldmatrix_x4(a[mt][0], a[mt][1], a[mt][2], a[mt][3], base + w * 4);
                }
                const uint32_t koff = half * 32 + kk * 8;
                #pragma unroll
                for (int ntp = 0; ntp < 2; ntp++) {
                    uint32_t b0, b1, b2, b3;
                    ldmatrix_x4(b0, b1, b2, b3,
                                base + (A_W + (b_row0 + ntp * 16) * B_ROW_W + koff + b_koff) * 4);
                    #pragma unroll
                    for (int mt = 0; mt < 2; mt++) {
                        mma_tf32(ctile[mt][ntp * 2],     a[mt][0], a[mt][1], a[mt][2], a[mt][3], b0, b1);
                        mma_tf32(ctile[mt][ntp * 2 + 1], a[mt][0], a[mt][1], a[mt][2], a[mt][3], b2, b3);
                    }
                }
            }
            #pragma unroll
            for (int mt = 0; mt < 2; mt++)
                #pragma unroll
                for (int nt = 0; nt < 4; nt++)
                    #pragma unroll
                    for (int i = 0; i < 4; i++) acc[mt][nt][i] += ctile[mt][nt][i];
        }
    }

    // epilogue: y = 0.9*acc + 0.1*Z0 ; ZT tf32 always; fp32 at last iter
    #pragma unroll
    for (int mt = 0; mt < 2; mt++) {
        #pragma unroll
        for (int nt = 0; nt < 4; nt++) {
            int r0 = bm + warpM * 32 + mt * 16 + (lane >> 2);
            int c0 = warpN * 32 + (nt >> 1) * 16 + (nt & 1) * 8 + (lane & 3) * 2;
            #pragma unroll
            for (int i = 0; i < 4; i++) {
                int r = r0 + ((i >= 2) ? 8 : 0);
                int c = c0 + (i & 1);
                size_t idx = (size_t)r * CLS + c;
                float y = 0.9f * acc[mt][nt][i] + 0.1f * g_Z0[idx];
                g_ZT[wb][c * N_ROWS + r] = f2tf32(y);
                if (it == NITER - 1) g_Zfinal[idx] = y;
            }
        }
    }
}

// ---------------- kernel 5: log_softmax ----------------
__global__ __launch_bounds__(256)
void lsm_kernel(float* __restrict__ out) {
    int row  = blockIdx.x * 8 + (threadIdx.x >> 5);
    int lane = threadIdx.x & 31;
    const float* zr = g_Zfinal + (size_t)row * CLS;
    float v0 = zr[lane], v1 = zr[lane + 32];
    float m = fmaxf(v0, v1);
    #pragma unroll
    for (int o = 16; o > 0; o >>= 1) m = fmaxf(m, __shfl_xor_sync(0xffffffffu, m, o));
    float e = expf(v0 - m) + expf(v1 - m);
    #pragma unroll
    for (int o = 16; o > 0; o >>= 1) e += __shfl_xor_sync(0xffffffffu, e, o);
    float l = m + logf(e);
    out[(size_t)row * CLS + lane]      = v0 - l;
    out[(size_t)row * CLS + lane + 32] = v1 - l;
}

// ---------------- launch ----------------
extern "C" void kernel_launch(void* const* d_in, const int* in_sizes, int n_in,
                              void* d_out, int out_size) {
    const float *h = nullptr, *adj = nullptr, *W1 = nullptr,
                *b1 = nullptr, *W2 = nullptr, *b2 = nullptr;
    for (int i = 0; i < n_in; i++) {
        switch (in_sizes[i]) {
            case N_ROWS * FEATS:  h   = (const float*)d_in[i]; break;
            case 268435456:       adj = (const float*)d_in[i]; break;
            case FEATS * HID:     W1  = (const float*)d_in[i]; break;
            case HID:             b1  = (const float*)d_in[i]; break;
            case HID * CLS:       W2  = (const float*)d_in[i]; break;
            case CLS:             b2  = (const float*)d_in[i]; break;
            default: break;
        }
    }

    cudaFuncSetAttribute(prop_kernel, cudaFuncAttributeMaxDynamicSharedMemorySize,
                         SMEM_BYTES);

    fuse_w_kernel<<<(FEATS * CLS + CLS + 255) / 256, 256>>>(W1, b1, W2, b2);
    z0_kernel<<<N_ROWS / Z0_BM, 256>>>(h);
    repack_kernel<<<N_ROWS / 8, 256>>>(adj);
    for (int it = 0; it < NITER; it++)
        prop_kernel<<<N_ROWS / BM, 256, SMEM_BYTES>>>(it);
    lsm_kernel<<<N_ROWS / 8, 256>>>((float*)d_out);
}

// round 14
// speedup vs baseline: 2.4177x; 1.6986x over previous
#include <cuda_runtime.h>
#include <cuda_bf16.h>
#include <cstdint>

#define N_ROWS 16384
#define FEATS  512
#define HID    256
#define CLS    64
#define NITER  10

// ---------------- scratch ----------------
__device__ float g_W[FEATS * CLS];
__device__ float g_bias[CLS];
__device__ float g_Z0[N_ROWS * CLS];
__device__ float g_Zfinal[N_ROWS * CLS];
__device__ __nv_bfloat16 g_ZTb[2][CLS * N_ROWS];            // Z^T [class][node], bf16
// adj as bf16 tiled images: [tile(128r)][stage(64k)] -> 128x64 bf16, granule-swizzled
__device__ uint32_t g_adjTb[(size_t)N_ROWS * N_ROWS / 2];

__device__ __forceinline__ uint32_t smem_u32_of(const void* p) {
    uint32_t a;
    asm("{ .reg .u64 t; cvta.to.shared.u64 t, %1; cvt.u32.u64 %0, t; }" : "=r"(a) : "l"(p));
    return a;
}
__device__ __forceinline__ void cp_async16(uint32_t smem, const void* gmem) {
    asm volatile("cp.async.cg.shared.global [%0], [%1], 16;\n" :: "r"(smem), "l"(gmem));
}
__device__ __forceinline__ void ldmatrix_x4(uint32_t& r0, uint32_t& r1,
                                            uint32_t& r2, uint32_t& r3, uint32_t a) {
    asm volatile("ldmatrix.sync.aligned.m8n8.x4.shared.b16 {%0,%1,%2,%3}, [%4];\n"
                 : "=r"(r0), "=r"(r1), "=r"(r2), "=r"(r3) : "r"(a));
}
__device__ __forceinline__ void mma_bf16(float c[4], const uint32_t a[4],
                                         uint32_t b0, uint32_t b1) {
    asm volatile(
        "mma.sync.aligned.m16n8k16.row.col.f32.bf16.bf16.f32 "
        "{%0,%1,%2,%3}, {%4,%5,%6,%7}, {%8,%9}, {%0,%1,%2,%3};\n"
        : "+f"(c[0]), "+f"(c[1]), "+f"(c[2]), "+f"(c[3])
        : "r"(a[0]), "r"(a[1]), "r"(a[2]), "r"(a[3]), "r"(b0), "r"(b1));
}

// ---------------- kernel 1: collapse the MLP ----------------
__global__ void fuse_w_kernel(const float* __restrict__ W1, const float* __restrict__ b1,
                              const float* __restrict__ W2, const float* __restrict__ b2) {
    int idx = blockIdx.x * blockDim.x + threadIdx.x;
    if (idx < FEATS * CLS) {
        int f = idx / CLS, c = idx % CLS;
        float s = 0.f;
        #pragma unroll 8
        for (int k = 0; k < HID; k++) s += W1[f * HID + k] * W2[k * CLS + c];
        g_W[idx] = s;
    } else if (idx < FEATS * CLS + CLS) {
        int c = idx - FEATS * CLS;
        float s = b2[c];
        for (int k = 0; k < HID; k++) s += b1[k] * W2[k * CLS + c];
        g_bias[c] = s;
    }
}

// ---------------- kernel 2: Z0 = h @ W + bias ----------------
#define Z0_BM 64
#define Z0_BK 16
__global__ __launch_bounds__(256)
void z0_kernel(const float* __restrict__ h) {
    __shared__ float As[Z0_BM][Z0_BK + 1];
    __shared__ float Bs[Z0_BK][CLS + 1];
    int bm = blockIdx.x * Z0_BM;
    int tx = threadIdx.x % 16, ty = threadIdx.x / 16;
    float acc[4][4];
    #pragma unroll
    for (int i = 0; i < 4; i++)
        #pragma unroll
        for (int j = 0; j < 4; j++) acc[i][j] = 0.f;

    for (int k0 = 0; k0 < FEATS; k0 += Z0_BK) {
        for (int i = threadIdx.x; i < Z0_BM * Z0_BK; i += 256) {
            int r = i / Z0_BK, c = i % Z0_BK;
            As[r][c] = h[(size_t)(bm + r) * FEATS + k0 + c];
        }
        for (int i = threadIdx.x; i < Z0_BK * CLS; i += 256) {
            int r = i / CLS, c = i % CLS;
            Bs[r][c] = g_W[(k0 + r) * CLS + c];
        }
        __syncthreads();
        #pragma unroll
        for (int kk = 0; kk < Z0_BK; kk++) {
            float a[4], b[4];
            #pragma unroll
            for (int i = 0; i < 4; i++) a[i] = As[ty * 4 + i][kk];
            #pragma unroll
            for (int j = 0; j < 4; j++) b[j] = Bs[kk][tx * 4 + j];
            #pragma unroll
            for (int i = 0; i < 4; i++)
                #pragma unroll
                for (int j = 0; j < 4; j++) acc[i][j] += a[i] * b[j];
        }
        __syncthreads();
    }
    #pragma unroll
    for (int i = 0; i < 4; i++)
        #pragma unroll
        for (int j = 0; j < 4; j++) {
            int r = bm + ty * 4 + i, c = tx * 4 + j;
            float y = acc[i][j] + g_bias[c];
            g_Z0[(size_t)r * CLS + c] = y;
            g_ZTb[0][c * N_ROWS + r] = __float2bfloat16_rn(y);
        }
}

// ---------------- kernel 3: repack adj -> bf16 tiled images ----------------
// block b: rows [8b, 8b+8). Each thread-iter converts one 16B out-granule (8 bf16).
__global__ __launch_bounds__(256)
void repack_kernel(const float* __restrict__ adj) {
    const int b = blockIdx.x;
    const int tid = threadIdx.x;
    #pragma unroll 4
    for (int j = 0; j < 64; j++) {
        int gfl = tid + j * 256;             // 0..16383 granules in this 8-row band
        int r_loc = gfl >> 11;               // 2048 granules per row
        int kg8 = gfl & 2047;                // granule within row (k = 8*kg8)
        int r = b * 8 + r_loc;
        const float4* src = (const float4*)(adj + (size_t)r * N_ROWS + kg8 * 8);
        float4 v0 = src[0], v1 = src[1];
        float f[8] = {v0.x, v0.y, v0.z, v0.w, v1.x, v1.y, v1.z, v1.w};
        uint16_t u[8];
        #pragma unroll
        for (int i = 0; i < 8; i++) {
            __nv_bfloat16 hb = __float2bfloat16_rn(f[i]);
            u[i] = *(uint16_t*)&hb;
        }
        int t  = r >> 7;
        int rl = r & 127;
        int s  = kg8 >> 3;                   // 8 granules (64 k) per stage
        int gi = kg8 & 7;
        int gsw = gi ^ (rl & 7);             // baked swizzle
        size_t off = ((size_t)(t * 256 + s)) * 4096 + rl * 32 + gsw * 4;
        *(uint4*)(g_adjTb + off) = *(uint4*)u;
    }
}

// ---------------- kernel 4: propagation (bf16 mma, 6-stage pipeline) ----------------
#define BM 128
#define SBK 64                 // k per stage
#define NST (N_ROWS / SBK)     // 256 stages
#define STAGES 6
#define A_W 4096               // words/stage: 128 rows x 32 words (64 bf16), swizzled
#define B_W 2048               // 64 class-rows x 32 words, swizzled
#define STAGE_W (A_W + B_W)    // 6144 words
#define SMEM_BYTES (STAGES * STAGE_W * 4)   // 147456

__global__ __launch_bounds__(256, 1)
void prop_kernel(int it) {
    const int rb = it & 1, wb = rb ^ 1;
    const __nv_bfloat16* ZTin = g_ZTb[rb];

    extern __shared__ uint32_t sm[];
    const uint32_t smem0 = smem_u32_of(sm);

    const int tid   = threadIdx.x;
    const int lane  = tid & 31;
    const int warp  = tid >> 5;
    const int warpM = warp >> 1;        // 0..3, 32 rows
    const int warpN = warp & 1;         // 0..1, 32 cols
    const int tile  = blockIdx.x;
    const int bm    = tile * BM;
    const int lr    = lane & 7;
    const int lg    = lane >> 3;

    auto load_stage = [&](int s, int st) {
        const uint32_t base = smem0 + (s * STAGE_W) * 4;
        const uint32_t* asrc = g_adjTb + ((size_t)(tile * 256 + st)) * 4096;
        #pragma unroll
        for (int j = 0; j < 4; j++) {          // A: 1024 contiguous 16B chunks
            int ch = tid + j * 256;
            cp_async16(base + ch * 16, asrc + ch * 4);
        }
        const int k0 = st * SBK;
        #pragma unroll
        for (int j = 0; j < 2; j++) {          // B: 512 granules of 8 bf16
            int ch = tid + j * 256;
            int c = ch >> 3, gi = ch & 7;
            cp_async16(base + (A_W + c * 32 + ((gi ^ (c & 7)) << 2)) * 4,
                       ZTin + (size_t)c * N_ROWS + k0 + gi * 8);
        }
        asm volatile("cp.async.commit_group;\n");
    };

    float acc[2][4][4];
    #pragma unroll
    for (int mt = 0; mt < 2; mt++)
        #pragma unroll
        for (int nt = 0; nt < 4; nt++)
            #pragma unroll
            for (int i = 0; i < 4; i++) acc[mt][nt][i] = 0.f;

    load_stage(0, 0);
    load_stage(1, 1);
    load_stage(2, 2);
    load_stage(3, 3);
    load_stage(4, 4);

    // fragment address precompute
    const uint32_t a_row0 = warpM * 32 + (lane & 15);       // + mt*16
    const uint32_t a_gadd = lane >> 4;                      // + kk*2
    const uint32_t b_row0 = warpN * 32 + (lg >> 1) * 8 + lr; // + ntp*16
    const uint32_t b_gadd = lg & 1;                         // + kk*2

    for (int st = 0; st < NST; st++) {
        asm volatile("cp.async.wait_group 4;\n");
        __syncthreads();

        int ns = st + 5;
        if (ns < NST) load_stage(ns % STAGES, ns);
        else          asm volatile("cp.async.commit_group;\n");

        const uint32_t base = smem0 + ((st % STAGES) * STAGE_W) * 4;

        #pragma unroll
        for (int half = 0; half < 2; half++) {
            float ctile[2][4][4];
            #pragma unroll
            for (int mt = 0; mt < 2; mt++)
                #pragma unroll
                for (int nt = 0; nt < 4; nt++)
                    #pragma unroll
                    for (int i = 0; i < 4; i++) ctile[mt][nt][i] = 0.f;

            #pragma unroll
            for (int kk2 = 0; kk2 < 2; kk2++) {       // k16 chunks
                const uint32_t kk = half * 2 + kk2;
                uint32_t a[2][4];
                #pragma unroll
                for (int mt = 0; mt < 2; mt++) {
                    uint32_t row = a_row0 + mt * 16;
                    uint32_t gi  = kk * 2 + a_gadd;
                    ldmatrix_x4(a[mt][0], a[mt][1], a[mt][2], a[mt][3],
                                base + (row * 32 + ((gi ^ (row & 7)) << 2)) * 4);
                }
                #pragma unroll
                for (int ntp = 0; ntp < 2; ntp++) {
                    uint32_t n  = b_row0 + ntp * 16;
                    uint32_t gi = kk * 2 + b_gadd;
                    uint32_t b0, b1, b2, b3;
                    ldmatrix_x4(b0, b1, b2, b3,
                                base + (A_W + n * 32 + ((gi ^ (n & 7)) << 2)) * 4);
                    #pragma unroll
                    for (int mt = 0; mt < 2; mt++) {
                        mma_bf16(ctile[mt][ntp * 2],     a[mt], b0, b1);
                        mma_bf16(ctile[mt][ntp * 2 + 1], a[mt], b2, b3);
                    }
                }
            }
            #pragma unroll
            for (int mt = 0; mt < 2; mt++)
                #pragma unroll
                for (int nt = 0; nt < 4; nt++)
                    #pragma unroll
                    for (int i = 0; i < 4; i++) acc[mt][nt][i] += ctile[mt][nt][i];
        }
    }

    // epilogue: y = 0.9*acc + 0.1*Z0 ; ZT bf16 always; fp32 at last iter
    #pragma unroll
    for (int mt = 0; mt < 2; mt++) {
        #pragma unroll
        for (int nt = 0; nt < 4; nt++) {
            int r0 = bm + warpM * 32 + mt * 16 + (lane >> 2);
            int c0 = warpN * 32 + (nt >> 1) * 16 + (nt & 1) * 8 + (lane & 3) * 2;
            #pragma unroll
            for (int i = 0; i < 4; i++) {
                int r = r0 + ((i >= 2) ? 8 : 0);
                int c = c0 + (i & 1);
                size_t idx = (size_t)r * CLS + c;
                float y = 0.9f * acc[mt][nt][i] + 0.1f * g_Z0[idx];
                g_ZTb[wb][c * N_ROWS + r] = __float2bfloat16_rn(y);
                if (it == NITER - 1) g_Zfinal[idx] = y;
            }
        }
    }
}

// ---------------- kernel 5: log_softmax ----------------
__global__ __launch_bounds__(256)
void lsm_kernel(float* __restrict__ out) {
    int row  = blockIdx.x * 8 + (threadIdx.x >> 5);
    int lane = threadIdx.x & 31;
    const float* zr = g_Zfinal + (size_t)row * CLS;
    float v0 = zr[lane], v1 = zr[lane + 32];
    float m = fmaxf(v0, v1);
    #pragma unroll
    for (int o = 16; o > 0; o >>= 1) m = fmaxf(m, __shfl_xor_sync(0xffffffffu, m, o));
    float e = expf(v0 - m) + expf(v1 - m);
    #pragma unroll
    for (int o = 16; o > 0; o >>= 1) e += __shfl_xor_sync(0xffffffffu, e, o);
    float l = m + logf(e);
    out[(size_t)row * CLS + lane]      = v0 - l;
    out[(size_t)row * CLS + lane + 32] = v1 - l;
}

// ---------------- launch ----------------
extern "C" void kernel_launch(void* const* d_in, const int* in_sizes, int n_in,
                              void* d_out, int out_size) {
    const float *h = nullptr, *adj = nullptr, *W1 = nullptr,
                *b1 = nullptr, *W2 = nullptr, *b2 = nullptr;
    for (int i = 0; i < n_in; i++) {
        switch (in_sizes[i]) {
            case N_ROWS * FEATS:  h   = (const float*)d_in[i]; break;
            case 268435456:       adj = (const float*)d_in[i]; break;
            case FEATS * HID:     W1  = (const float*)d_in[i]; break;
            case HID:             b1  = (const float*)d_in[i]; break;
            case HID * CLS:       W2  = (const float*)d_in[i]; break;
            case CLS:             b2  = (const float*)d_in[i]; break;
            default: break;
        }
    }

    cudaFuncSetAttribute(prop_kernel, cudaFuncAttributeMaxDynamicSharedMemorySize,
                         SMEM_BYTES);

    fuse_w_kernel<<<(FEATS * CLS + CLS + 255) / 256, 256>>>(W1, b1, W2, b2);
    z0_kernel<<<N_ROWS / Z0_BM, 256>>>(h);
    repack_kernel<<<N_ROWS / 8, 256>>>(adj);
    for (int it = 0; it < NITER; it++)
        prop_kernel<<<N_ROWS / BM, 256, SMEM_BYTES>>>(it);
    lsm_kernel<<<N_ROWS / 8, 256>>>((float*)d_out);
}

// round 15
// speedup vs baseline: 2.4430x; 1.0105x over previous
#include <cuda_runtime.h>
#include <cuda_bf16.h>
#include <cstdint>

#define N_ROWS 16384
#define FEATS  512
#define HID    256
#define CLS    64
#define NITER  10

// ---------------- scratch ----------------
__device__ float g_W[FEATS * CLS];
__device__ float g_bias[CLS];
__device__ float g_Z0[N_ROWS * CLS];
__device__ float g_Zfinal[N_ROWS * CLS];
__device__ __nv_bfloat16 g_ZTb[2][CLS * N_ROWS];            // Z^T [class][node], bf16
// adj bf16 tiled images: [tile(64r)][stage(64k)] -> 64x64 bf16, granule-swizzled
__device__ uint32_t g_adjTb[(size_t)N_ROWS * N_ROWS / 2];

__device__ __forceinline__ uint32_t smem_u32_of(const void* p) {
    uint32_t a;
    asm("{ .reg .u64 t; cvta.to.shared.u64 t, %1; cvt.u32.u64 %0, t; }" : "=r"(a) : "l"(p));
    return a;
}
__device__ __forceinline__ void cp_async16(uint32_t smem, const void* gmem) {
    asm volatile("cp.async.cg.shared.global [%0], [%1], 16;\n" :: "r"(smem), "l"(gmem));
}
__device__ __forceinline__ void ldmatrix_x4(uint32_t& r0, uint32_t& r1,
                                            uint32_t& r2, uint32_t& r3, uint32_t a) {
    asm volatile("ldmatrix.sync.aligned.m8n8.x4.shared.b16 {%0,%1,%2,%3}, [%4];\n"
                 : "=r"(r0), "=r"(r1), "=r"(r2), "=r"(r3) : "r"(a));
}
__device__ __forceinline__ void mma_bf16(float c[4], const uint32_t a[4],
                                         uint32_t b0, uint32_t b1) {
    asm volatile(
        "mma.sync.aligned.m16n8k16.row.col.f32.bf16.bf16.f32 "
        "{%0,%1,%2,%3}, {%4,%5,%6,%7}, {%8,%9}, {%0,%1,%2,%3};\n"
        : "+f"(c[0]), "+f"(c[1]), "+f"(c[2]), "+f"(c[3])
        : "r"(a[0]), "r"(a[1]), "r"(a[2]), "r"(a[3]), "r"(b0), "r"(b1));
}

// ---------------- kernel 1: collapse the MLP ----------------
__global__ void fuse_w_kernel(const float* __restrict__ W1, const float* __restrict__ b1,
                              const float* __restrict__ W2, const float* __restrict__ b2) {
    int idx = blockIdx.x * blockDim.x + threadIdx.x;
    if (idx < FEATS * CLS) {
        int f = idx / CLS, c = idx % CLS;
        float s = 0.f;
        #pragma unroll 8
        for (int k = 0; k < HID; k++) s += W1[f * HID + k] * W2[k * CLS + c];
        g_W[idx] = s;
    } else if (idx < FEATS * CLS + CLS) {
        int c = idx - FEATS * CLS;
        float s = b2[c];
        for (int k = 0; k < HID; k++) s += b1[k] * W2[k * CLS + c];
        g_bias[c] = s;
    }
}

// ---------------- kernel 2: Z0 = h @ W + bias ----------------
#define Z0_BM 64
#define Z0_BK 16
__global__ __launch_bounds__(256)
void z0_kernel(const float* __restrict__ h) {
    __shared__ float As[Z0_BM][Z0_BK + 1];
    __shared__ float Bs[Z0_BK][CLS + 1];
    int bm = blockIdx.x * Z0_BM;
    int tx = threadIdx.x % 16, ty = threadIdx.x / 16;
    float acc[4][4];
    #pragma unroll
    for (int i = 0; i < 4; i++)
        #pragma unroll
        for (int j = 0; j < 4; j++) acc[i][j] = 0.f;

    for (int k0 = 0; k0 < FEATS; k0 += Z0_BK) {
        for (int i = threadIdx.x; i < Z0_BM * Z0_BK; i += 256) {
            int r = i / Z0_BK, c = i % Z0_BK;
            As[r][c] = h[(size_t)(bm + r) * FEATS + k0 + c];
        }
        for (int i = threadIdx.x; i < Z0_BK * CLS; i += 256) {
            int r = i / CLS, c = i % CLS;
            Bs[r][c] = g_W[(k0 + r) * CLS + c];
        }
        __syncthreads();
        #pragma unroll
        for (int kk = 0; kk < Z0_BK; kk++) {
            float a[4], b[4];
            #pragma unroll
            for (int i = 0; i < 4; i++) a[i] = As[ty * 4 + i][kk];
            #pragma unroll
            for (int j = 0; j < 4; j++) b[j] = Bs[kk][tx * 4 + j];
            #pragma unroll
            for (int i = 0; i < 4; i++)
                #pragma unroll
                for (int j = 0; j < 4; j++) acc[i][j] += a[i] * b[j];
        }
        __syncthreads();
    }
    #pragma unroll
    for (int i = 0; i < 4; i++)
        #pragma unroll
        for (int j = 0; j < 4; j++) {
            int r = bm + ty * 4 + i, c = tx * 4 + j;
            float y = acc[i][j] + g_bias[c];
            g_Z0[(size_t)r * CLS + c] = y;
            g_ZTb[0][c * N_ROWS + r] = __float2bfloat16_rn(y);
        }
}

// ---------------- kernel 3: repack adj -> bf16 64-row tile images ----------------
__global__ __launch_bounds__(256)
void repack_kernel(const float* __restrict__ adj) {
    const int b = blockIdx.x;
    const int tid = threadIdx.x;
    #pragma unroll 4
    for (int j = 0; j < 64; j++) {
        int gfl = tid + j * 256;             // 0..16383 granules in this 8-row band
        int r_loc = gfl >> 11;               // 2048 granules per row
        int kg8 = gfl & 2047;                // granule within row (k = 8*kg8)
        int r = b * 8 + r_loc;
        const float4* src = (const float4*)(adj + (size_t)r * N_ROWS + kg8 * 8);
        float4 v0 = src[0], v1 = src[1];
        float f[8] = {v0.x, v0.y, v0.z, v0.w, v1.x, v1.y, v1.z, v1.w};
        uint16_t u[8];
        #pragma unroll
        for (int i = 0; i < 8; i++) {
            __nv_bfloat16 hb = __float2bfloat16_rn(f[i]);
            u[i] = *(uint16_t*)&hb;
        }
        int t  = r >> 6;                     // 64-row tile
        int rl = r & 63;
        int s  = kg8 >> 3;                   // 8 granules (64 k) per stage
        int gi = kg8 & 7;
        int gsw = gi ^ (rl & 7);             // baked swizzle
        size_t off = ((size_t)(t * 256 + s)) * 2048 + rl * 32 + gsw * 4;
        *(uint4*)(g_adjTb + off) = *(uint4*)u;
    }
}

// ---------------- kernel 4: propagation (bf16 mma, BM=64, 2 CTAs/SM) ----------------
#define BM 64
#define SBK 64                 // k per stage
#define NST (N_ROWS / SBK)     // 256 stages
#define STAGES 6
#define A_W 2048               // words/stage: 64 rows x 32 words (64 bf16), swizzled
#define B_W 2048               // 64 class-rows x 32 words, swizzled
#define STAGE_W (A_W + B_W)    // 4096 words
#define SMEM_BYTES (STAGES * STAGE_W * 4)   // 98304

__global__ __launch_bounds__(256, 2)
void prop_kernel(int it) {
    const int rb = it & 1, wb = rb ^ 1;
    const __nv_bfloat16* ZTin = g_ZTb[rb];

    extern __shared__ uint32_t sm[];
    const uint32_t smem0 = smem_u32_of(sm);

    const int tid   = threadIdx.x;
    const int lane  = tid & 31;
    const int warp  = tid >> 5;
    const int warpM = warp >> 1;        // 0..3, 16 rows each
    const int warpN = warp & 1;         // 0..1, 32 cols each
    const int tile  = blockIdx.x;
    const int bm    = tile * BM;
    const int lr    = lane & 7;
    const int lg    = lane >> 3;

    auto load_stage = [&](int s, int st) {
        const uint32_t base = smem0 + (s * STAGE_W) * 4;
        const uint32_t* asrc = g_adjTb + ((size_t)(tile * 256 + st)) * 2048;
        #pragma unroll
        for (int j = 0; j < 2; j++) {          // A: 512 contiguous 16B chunks
            int ch = tid + j * 256;
            cp_async16(base + ch * 16, asrc + ch * 4);
        }
        const int k0 = st * SBK;
        #pragma unroll
        for (int j = 0; j < 2; j++) {          // B: 512 granules of 8 bf16
            int ch = tid + j * 256;
            int c = ch >> 3, gi = ch & 7;
            cp_async16(base + (A_W + c * 32 + ((gi ^ (c & 7)) << 2)) * 4,
                       ZTin + (size_t)c * N_ROWS + k0 + gi * 8);
        }
        asm volatile("cp.async.commit_group;\n");
    };

    float acc[4][4];
    #pragma unroll
    for (int nt = 0; nt < 4; nt++)
        #pragma unroll
        for (int i = 0; i < 4; i++) acc[nt][i] = 0.f;

    load_stage(0, 0);
    load_stage(1, 1);
    load_stage(2, 2);
    load_stage(3, 3);
    load_stage(4, 4);

    const uint32_t a_row0 = warpM * 16 + (lane & 15);
    const uint32_t a_gadd = lane >> 4;                       // + kk*2
    const uint32_t b_row0 = warpN * 32 + (lg >> 1) * 8 + lr; // + ntp*16
    const uint32_t b_gadd = lg & 1;                          // + kk*2

    for (int st = 0; st < NST; st++) {
        asm volatile("cp.async.wait_group 4;\n");
        __syncthreads();

        int ns = st + 5;
        if (ns < NST) load_stage(ns % STAGES, ns);
        else          asm volatile("cp.async.commit_group;\n");

        const uint32_t base = smem0 + ((st % STAGES) * STAGE_W) * 4;

        #pragma unroll
        for (int half = 0; half < 2; half++) {
            float ctile[4][4];
            #pragma unroll
            for (int nt = 0; nt < 4; nt++)
                #pragma unroll
                for (int i = 0; i < 4; i++) ctile[nt][i] = 0.f;

            #pragma unroll
            for (int kk2 = 0; kk2 < 2; kk2++) {       // k16 chunks
                const uint32_t kk = half * 2 + kk2;
                uint32_t a[4];
                {
                    uint32_t gi = kk * 2 + a_gadd;
                    ldmatrix_x4(a[0], a[1], a[2], a[3],
                                base + (a_row0 * 32 + ((gi ^ (a_row0 & 7)) << 2)) * 4);
                }
                #pragma unroll
                for (int ntp = 0; ntp < 2; ntp++) {
                    uint32_t n  = b_row0 + ntp * 16;
                    uint32_t gi = kk * 2 + b_gadd;
                    uint32_t b0, b1, b2, b3;
                    ldmatrix_x4(b0, b1, b2, b3,
                                base + (A_W + n * 32 + ((gi ^ (n & 7)) << 2)) * 4);
                    mma_bf16(ctile[ntp * 2],     a, b0, b1);
                    mma_bf16(ctile[ntp * 2 + 1], a, b2, b3);
                }
            }
            #pragma unroll
            for (int nt = 0; nt < 4; nt++)
                #pragma unroll
                for (int i = 0; i < 4; i++) acc[nt][i] += ctile[nt][i];
        }
    }

    // epilogue: y = 0.9*acc + 0.1*Z0 ; ZT bf16 always; fp32 at last iter
    #pragma unroll
    for (int nt = 0; nt < 4; nt++) {
        int r0 = bm + warpM * 16 + (lane >> 2);
        int c0 = warpN * 32 + (nt >> 1) * 16 + (nt & 1) * 8 + (lane & 3) * 2;
        #pragma unroll
        for (int i = 0; i < 4; i++) {
            int r = r0 + ((i >= 2) ? 8 : 0);
            int c = c0 + (i & 1);
            size_t idx = (size_t)r * CLS + c;
            float y = 0.9f * acc[nt][i] + 0.1f * g_Z0[idx];
            g_ZTb[wb][c * N_ROWS + r] = __float2bfloat16_rn(y);
            if (it == NITER - 1) g_Zfinal[idx] = y;
        }
    }
}

// ---------------- kernel 5: log_softmax ----------------
__global__ __launch_bounds__(256)
void lsm_kernel(float* __restrict__ out) {
    int row  = blockIdx.x * 8 + (threadIdx.x >> 5);
    int lane = threadIdx.x & 31;
    const float* zr = g_Zfinal + (size_t)row * CLS;
    float v0 = zr[lane], v1 = zr[lane + 32];
    float m = fmaxf(v0, v1);
    #pragma unroll
    for (int o = 16; o > 0; o >>= 1) m = fmaxf(m, __shfl_xor_sync(0xffffffffu, m, o));
    float e = expf(v0 - m) + expf(v1 - m);
    #pragma unroll
    for (int o = 16; o > 0; o >>= 1) e += __shfl_xor_sync(0xffffffffu, e, o);
    float l = m + logf(e);
    out[(size_t)row * CLS + lane]      = v0 - l;
    out[(size_t)row * CLS + lane + 32] = v1 - l;
}

// ---------------- launch ----------------
extern "C" void kernel_launch(void* const* d_in, const int* in_sizes, int n_in,
                              void* d_out, int out_size) {
    const float *h = nullptr, *adj = nullptr, *W1 = nullptr,
                *b1 = nullptr, *W2 = nullptr, *b2 = nullptr;
    for (int i = 0; i < n_in; i++) {
        switch (in_sizes[i]) {
            case N_ROWS * FEATS:  h   = (const float*)d_in[i]; break;
            case 268435456:       adj = (const float*)d_in[i]; break;
            case FEATS * HID:     W1  = (const float*)d_in[i]; break;
            case HID:             b1  = (const float*)d_in[i]; break;
            case HID * CLS:       W2  = (const float*)d_in[i]; break;
            case CLS:             b2  = (const float*)d_in[i]; break;
            default: break;
        }
    }

    cudaFuncSetAttribute(prop_kernel, cudaFuncAttributeMaxDynamicSharedMemorySize,
                         SMEM_BYTES);

    fuse_w_kernel<<<(FEATS * CLS + CLS + 255) / 256, 256>>>(W1, b1, W2, b2);
    z0_kernel<<<N_ROWS / Z0_BM, 256>>>(h);
    repack_kernel<<<N_ROWS / 8, 256>>>(adj);
    for (int it = 0; it < NITER; it++)
        prop_kernel<<<N_ROWS / BM, 256, SMEM_BYTES>>>(it);
    lsm_kernel<<<N_ROWS / 8, 256>>>((float*)d_out);
}

// round 16
// speedup vs baseline: 2.5907x; 1.0605x over previous
#include <cuda_runtime.h>
#include <cuda_bf16.h>
#include <cstdint>

#define N_ROWS 16384
#define FEATS  512
#define HID    256
#define CLS    64
#define NITER  10

// ---------------- scratch ----------------
__device__ float g_W[FEATS * CLS];
__device__ float g_bias[CLS];
__device__ float g_Z0[N_ROWS * CLS];
__device__ float g_Zfinal[N_ROWS * CLS];
__device__ __nv_bfloat16 g_ZTb[2][CLS * N_ROWS];            // Z^T [class][node], bf16
// adj bf16 tiled images: [tile(128r)][stage(128k)] -> 128x128 bf16 (32KB), swizzled
__device__ uint32_t g_adjTb[(size_t)N_ROWS * N_ROWS / 2];

__device__ __forceinline__ uint32_t smem_u32_of(const void* p) {
    uint32_t a;
    asm("{ .reg .u64 t; cvta.to.shared.u64 t, %1; cvt.u32.u64 %0, t; }" : "=r"(a) : "l"(p));
    return a;
}
__device__ __forceinline__ void cp_async16(uint32_t smem, const void* gmem) {
    asm volatile("cp.async.cg.shared.global [%0], [%1], 16;\n" :: "r"(smem), "l"(gmem));
}
__device__ __forceinline__ void ldmatrix_x4(uint32_t& r0, uint32_t& r1,
                                            uint32_t& r2, uint32_t& r3, uint32_t a) {
    asm volatile("ldmatrix.sync.aligned.m8n8.x4.shared.b16 {%0,%1,%2,%3}, [%4];\n"
                 : "=r"(r0), "=r"(r1), "=r"(r2), "=r"(r3) : "r"(a));
}
__device__ __forceinline__ void mma_bf16(float c[4], const uint32_t a[4],
                                         uint32_t b0, uint32_t b1) {
    asm volatile(
        "mma.sync.aligned.m16n8k16.row.col.f32.bf16.bf16.f32 "
        "{%0,%1,%2,%3}, {%4,%5,%6,%7}, {%8,%9}, {%0,%1,%2,%3};\n"
        : "+f"(c[0]), "+f"(c[1]), "+f"(c[2]), "+f"(c[3])
        : "r"(a[0]), "r"(a[1]), "r"(a[2]), "r"(a[3]), "r"(b0), "r"(b1));
}

// ---------------- kernel 1: collapse the MLP ----------------
__global__ void fuse_w_kernel(const float* __restrict__ W1, const float* __restrict__ b1,
                              const float* __restrict__ W2, const float* __restrict__ b2) {
    int idx = blockIdx.x * blockDim.x + threadIdx.x;
    if (idx < FEATS * CLS) {
        int f = idx / CLS, c = idx % CLS;
        float s = 0.f;
        #pragma unroll 8
        for (int k = 0; k < HID; k++) s += W1[f * HID + k] * W2[k * CLS + c];
        g_W[idx] = s;
    } else if (idx < FEATS * CLS + CLS) {
        int c = idx - FEATS * CLS;
        float s = b2[c];
        for (int k = 0; k < HID; k++) s += b1[k] * W2[k * CLS + c];
        g_bias[c] = s;
    }
}

// ---------------- kernel 2: Z0 = h @ W + bias ----------------
#define Z0_BM 64
#define Z0_BK 16
__global__ __launch_bounds__(256)
void z0_kernel(const float* __restrict__ h) {
    __shared__ float As[Z0_BM][Z0_BK + 1];
    __shared__ float Bs[Z0_BK][CLS + 1];
    int bm = blockIdx.x * Z0_BM;
    int tx = threadIdx.x % 16, ty = threadIdx.x / 16;
    float acc[4][4];
    #pragma unroll
    for (int i = 0; i < 4; i++)
        #pragma unroll
        for (int j = 0; j < 4; j++) acc[i][j] = 0.f;

    for (int k0 = 0; k0 < FEATS; k0 += Z0_BK) {
        for (int i = threadIdx.x; i < Z0_BM * Z0_BK; i += 256) {
            int r = i / Z0_BK, c = i % Z0_BK;
            As[r][c] = h[(size_t)(bm + r) * FEATS + k0 + c];
        }
        for (int i = threadIdx.x; i < Z0_BK * CLS; i += 256) {
            int r = i / CLS, c = i % CLS;
            Bs[r][c] = g_W[(k0 + r) * CLS + c];
        }
        __syncthreads();
        #pragma unroll
        for (int kk = 0; kk < Z0_BK; kk++) {
            float a[4], b[4];
            #pragma unroll
            for (int i = 0; i < 4; i++) a[i] = As[ty * 4 + i][kk];
            #pragma unroll
            for (int j = 0; j < 4; j++) b[j] = Bs[kk][tx * 4 + j];
            #pragma unroll
            for (int i = 0; i < 4; i++)
                #pragma unroll
                for (int j = 0; j < 4; j++) acc[i][j] += a[i] * b[j];
        }
        __syncthreads();
    }
    #pragma unroll
    for (int i = 0; i < 4; i++)
        #pragma unroll
        for (int j = 0; j < 4; j++) {
            int r = bm + ty * 4 + i, c = tx * 4 + j;
            float y = acc[i][j] + g_bias[c];
            g_Z0[(size_t)r * CLS + c] = y;
            g_ZTb[0][c * N_ROWS + r] = __float2bfloat16_rn(y);
        }
}

// ---------------- kernel 3: repack adj -> bf16 images (output-major) ----------------
// Image (t,s): 128 rows x 128 k = 32 KB, row = 256B, granule-swizzled.
// Each block emits 4 consecutive images; writes perfectly contiguous.
__global__ __launch_bounds__(256)
void repack_kernel(const float* __restrict__ adj) {
    const int tid = threadIdx.x;
    #pragma unroll
    for (int im = 0; im < 4; im++) {
        int img = blockIdx.x * 4 + im;
        int t = img >> 7, s = img & 127;
        uint32_t* dst = g_adjTb + (size_t)img * 8192;
        #pragma unroll
        for (int j = 0; j < 8; j++) {
            int go = tid + j * 256;          // out granule 0..2047
            int rl = go >> 4, gsw = go & 15;
            int gi = gsw ^ (rl & 7);
            const float4* src = (const float4*)(adj +
                (size_t)(t * 128 + rl) * N_ROWS + s * 128 + gi * 8);
            float4 v0 = src[0], v1 = src[1];
            float f[8] = {v0.x, v0.y, v0.z, v0.w, v1.x, v1.y, v1.z, v1.w};
            uint16_t u[8];
            #pragma unroll
            for (int i = 0; i < 8; i++) {
                __nv_bfloat16 hb = __float2bfloat16_rn(f[i]);
                u[i] = *(uint16_t*)&hb;
            }
            *(uint4*)(dst + rl * 64 + gsw * 4) = *(uint4*)u;
        }
    }
}

// ---------------- kernel 4: propagation (bf16 mma, BM=128, SBK=128) ----------------
#define BM 128
#define SBK 128                // k per stage
#define NST (N_ROWS / SBK)     // 128 stages
#define STAGES 3
#define A_W 8192               // words/stage: 128 rows x 64 words (128 bf16), swizzled
#define B_W 4096               // 64 class-rows x 64 words, swizzled
#define STAGE_W (A_W + B_W)    // 12288 words = 48 KB
#define SMEM_BYTES (STAGES * STAGE_W * 4)   // 147456

__global__ __launch_bounds__(256, 1)
void prop_kernel(int it) {
    const int rb = it & 1, wb = rb ^ 1;
    const __nv_bfloat16* ZTin = g_ZTb[rb];

    extern __shared__ uint32_t sm[];
    const uint32_t smem0 = smem_u32_of(sm);

    const int tid   = threadIdx.x;
    const int lane  = tid & 31;
    const int warp  = tid >> 5;
    const int warpM = warp >> 1;        // 0..3, 32 rows
    const int warpN = warp & 1;         // 0..1, 32 cols
    const int tile  = blockIdx.x;
    const int bm    = tile * BM;
    const int lr    = lane & 7;
    const int lg    = lane >> 3;

    auto load_stage = [&](int s, int st) {
        const uint32_t base = smem0 + (s * STAGE_W) * 4;
        const uint32_t* asrc = g_adjTb + ((size_t)(tile * NST + st)) * 8192;
        #pragma unroll
        for (int j = 0; j < 8; j++) {          // A: 2048 contiguous 16B chunks
            int ch = tid + j * 256;
            cp_async16(base + ch * 16, asrc + ch * 4);
        }
        const int k0 = st * SBK;
        #pragma unroll
        for (int j = 0; j < 4; j++) {          // B: 1024 granules of 8 bf16
            int ch = tid + j * 256;
            int c = ch >> 4, gi = ch & 15;
            cp_async16(base + (A_W + c * 64 + ((gi ^ (c & 7)) << 2)) * 4,
                       ZTin + (size_t)c * N_ROWS + k0 + gi * 8);
        }
        asm volatile("cp.async.commit_group;\n");
    };

    float acc[2][4][4];
    #pragma unroll
    for (int mt = 0; mt < 2; mt++)
        #pragma unroll
        for (int nt = 0; nt < 4; nt++)
            #pragma unroll
            for (int i = 0; i < 4; i++) acc[mt][nt][i] = 0.f;

    load_stage(0, 0);
    load_stage(1, 1);

    const uint32_t a_row0 = warpM * 32 + (lane & 15);        // + mt*16
    const uint32_t a_gadd = lane >> 4;                       // + kglobal*2
    const uint32_t b_row0 = warpN * 32 + (lg >> 1) * 8 + lr; // + ntp*16
    const uint32_t b_gadd = lg & 1;                          // + kglobal*2

    for (int st = 0; st < NST; st++) {
        asm volatile("cp.async.wait_group 1;\n");
        __syncthreads();

        int ns = st + 2;
        if (ns < NST) load_stage(ns % STAGES, ns);
        else          asm volatile("cp.async.commit_group;\n");

        const uint32_t base = smem0 + ((st % STAGES) * STAGE_W) * 4;

        #pragma unroll
        for (int half = 0; half < 4; half++) {       // 4 x 32k, reacc each
            float ctile[2][4][4];
            #pragma unroll
            for (int mt = 0; mt < 2; mt++)
                #pragma unroll
                for (int nt = 0; nt < 4; nt++)
                    #pragma unroll
                    for (int i = 0; i < 4; i++) ctile[mt][nt][i] = 0.f;

            #pragma unroll
            for (int kk2 = 0; kk2 < 2; kk2++) {      // k16 chunks
                const uint32_t kg = half * 2 + kk2;  // 0..7
                uint32_t a[2][4];
                #pragma unroll
                for (int mt = 0; mt < 2; mt++) {
                    uint32_t row = a_row0 + mt * 16;
                    uint32_t gi  = kg * 2 + a_gadd;
                    ldmatrix_x4(a[mt][0], a[mt][1], a[mt][2], a[mt][3],
                                base + (row * 64 + ((gi ^ (row & 7)) << 2)) * 4);
                }
                #pragma unroll
                for (int ntp = 0; ntp < 2; ntp++) {
                    uint32_t n  = b_row0 + ntp * 16;
                    uint32_t gi = kg * 2 + b_gadd;
                    uint32_t b0, b1, b2, b3;
                    ldmatrix_x4(b0, b1, b2, b3,
                                base + (A_W + n * 64 + ((gi ^ (n & 7)) << 2)) * 4);
                    #pragma unroll
                    for (int mt = 0; mt < 2; mt++) {
                        mma_bf16(ctile[mt][ntp * 2],     a[mt], b0, b1);
                        mma_bf16(ctile[mt][ntp * 2 + 1], a[mt], b2, b3);
                    }
                }
            }
            #pragma unroll
            for (int mt = 0; mt < 2; mt++)
                #pragma unroll
                for (int nt = 0; nt < 4; nt++)
                    #pragma unroll
                    for (int i = 0; i < 4; i++) acc[mt][nt][i] += ctile[mt][nt][i];
        }
    }

    // epilogue: y = 0.9*acc + 0.1*Z0 ; ZT bf16 always; fp32 at last iter
    #pragma unroll
    for (int mt = 0; mt < 2; mt++) {
        #pragma unroll
        for (int nt = 0; nt < 4; nt++) {
            int r0 = bm + warpM * 32 + mt * 16 + (lane >> 2);
            int c0 = warpN * 32 + (nt >> 1) * 16 + (nt & 1) * 8 + (lane & 3) * 2;
            #pragma unroll
            for (int i = 0; i < 4; i++) {
                int r = r0 + ((i >= 2) ? 8 : 0);
                int c = c0 + (i & 1);
                size_t idx = (size_t)r * CLS + c;
                float y = 0.9f * acc[mt][nt][i] + 0.1f * g_Z0[idx];
                g_ZTb[wb][c * N_ROWS + r] = __float2bfloat16_rn(y);
                if (it == NITER - 1) g_Zfinal[idx] = y;
            }
        }
    }
}

// ---------------- kernel 5: log_softmax ----------------
__global__ __launch_bounds__(256)
void lsm_kernel(float* __restrict__ out) {
    int row  = blockIdx.x * 8 + (threadIdx.x >> 5);
    int lane = threadIdx.x & 31;
    const float* zr = g_Zfinal + (size_t)row * CLS;
    float v0 = zr[lane], v1 = zr[lane + 32];
    float m = fmaxf(v0, v1);
    #pragma unroll
    for (int o = 16; o > 0; o >>= 1) m = fmaxf(m, __shfl_xor_sync(0xffffffffu, m, o));
    float e = expf(v0 - m) + expf(v1 - m);
    #pragma unroll
    for (int o = 16; o > 0; o >>= 1) e += __shfl_xor_sync(0xffffffffu, e, o);
    float l = m + logf(e);
    out[(size_t)row * CLS + lane]      = v0 - l;
    out[(size_t)row * CLS + lane + 32] = v1 - l;
}

// ---------------- launch ----------------
extern "C" void kernel_launch(void* const* d_in, const int* in_sizes, int n_in,
                              void* d_out, int out_size) {
    const float *h = nullptr, *adj = nullptr, *W1 = nullptr,
                *b1 = nullptr, *W2 = nullptr, *b2 = nullptr;
    for (int i = 0; i < n_in; i++) {
        switch (in_sizes[i]) {
            case N_ROWS * FEATS:  h   = (const float*)d_in[i]; break;
            case 268435456:       adj = (const float*)d_in[i]; break;
            case FEATS * HID:     W1  = (const float*)d_in[i]; break;
            case HID:             b1  = (const float*)d_in[i]; break;
            case HID * CLS:       W2  = (const float*)d_in[i]; break;
            case CLS:             b2  = (const float*)d_in[i]; break;
            default: break;
        }
    }

    cudaFuncSetAttribute(prop_kernel, cudaFuncAttributeMaxDynamicSharedMemorySize,
                         SMEM_BYTES);

    fuse_w_kernel<<<(FEATS * CLS + CLS + 255) / 256, 256>>>(W1, b1, W2, b2);
    z0_kernel<<<N_ROWS / Z0_BM, 256>>>(h);
    repack_kernel<<<(N_ROWS / BM) * NST / 4, 256>>>(adj);   // 4096 blocks
    for (int it = 0; it < NITER; it++)
        prop_kernel<<<N_ROWS / BM, 256, SMEM_BYTES>>>(it);
    lsm_kernel<<<N_ROWS / 8, 256>>>((float*)d_out);
}